// round 1
// baseline (speedup 1.0000x reference)
#include <cuda_runtime.h>
#include <math.h>

#define SEQ   2048
#define HID   4096
#define NH    32
#define NKV   8
#define HD    128
#define GRP   (NH / NKV)             // 4
#define QKVN  ((NH + 2 * NKV) * HD)  // 6144
#define ATTN_N (NH * HD)             // 4096

// Scratch (no allocations allowed)
__device__ float g_qkv[SEQ * QKVN];     // ~50 MB
__device__ float g_attn[SEQ * ATTN_N];  // ~33 MB

// ---------------------------------------------------------------------------
// SGEMM: C[M,N] = A[M,K] * B[K,N], row-major, M%128==0, N%128==0, K%16==0
// 128x128 block tile, 8x8 per thread, 256 threads.
// ---------------------------------------------------------------------------
__global__ __launch_bounds__(256, 2)
void sgemm_kernel(const float* __restrict__ A, const float* __restrict__ B,
                  float* __restrict__ C, int M, int N, int K)
{
    const int BM = 128, BN = 128, BK = 16;
    __shared__ float As[BK][BM + 4];  // padded: conflict-light transposed stores
    __shared__ float Bs[BK][BN];

    int tid = threadIdx.x;
    int bm = blockIdx.y, bn = blockIdx.x;
    int tx = tid & 15, ty = tid >> 4;

    float acc[8][8];
#pragma unroll
    for (int i = 0; i < 8; i++)
#pragma unroll
        for (int j = 0; j < 8; j++) acc[i][j] = 0.f;

    const float* Ablk = A + (size_t)bm * BM * K;
    const float* Bblk = B + (size_t)bn * BN;

    for (int kt = 0; kt < K; kt += BK) {
        // Load A tile (128x16) transposed into As[k][m]
#pragma unroll
        for (int i = tid; i < BM * BK / 4; i += 256) {
            int r = i >> 2;            // 0..127
            int c4 = (i & 3) * 4;      // 0,4,8,12
            float4 a = *(const float4*)(Ablk + (size_t)r * K + kt + c4);
            As[c4 + 0][r] = a.x;
            As[c4 + 1][r] = a.y;
            As[c4 + 2][r] = a.z;
            As[c4 + 3][r] = a.w;
        }
        // Load B tile (16x128) row-major
#pragma unroll
        for (int i = tid; i < BK * BN / 4; i += 256) {
            int r = i >> 5;            // 0..15
            int c4 = (i & 31) * 4;     // 0..124
            *(float4*)&Bs[r][c4] =
                *(const float4*)(Bblk + (size_t)(kt + r) * N + c4);
        }
        __syncthreads();

#pragma unroll
        for (int k = 0; k < BK; k++) {
            float ra[8], rb[8];
            float4 a0 = *(const float4*)&As[k][ty * 8];
            float4 a1 = *(const float4*)&As[k][ty * 8 + 4];
            float4 b0 = *(const float4*)&Bs[k][tx * 8];
            float4 b1 = *(const float4*)&Bs[k][tx * 8 + 4];
            ra[0] = a0.x; ra[1] = a0.y; ra[2] = a0.z; ra[3] = a0.w;
            ra[4] = a1.x; ra[5] = a1.y; ra[6] = a1.z; ra[7] = a1.w;
            rb[0] = b0.x; rb[1] = b0.y; rb[2] = b0.z; rb[3] = b0.w;
            rb[4] = b1.x; rb[5] = b1.y; rb[6] = b1.z; rb[7] = b1.w;
#pragma unroll
            for (int i = 0; i < 8; i++)
#pragma unroll
                for (int j = 0; j < 8; j++)
                    acc[i][j] += ra[i] * rb[j];
        }
        __syncthreads();
    }

    // Write C
#pragma unroll
    for (int i = 0; i < 8; i++) {
        int row = bm * BM + ty * 8 + i;
        float* crow = C + (size_t)row * N + bn * BN + tx * 8;
        *(float4*)(crow)     = make_float4(acc[i][0], acc[i][1], acc[i][2], acc[i][3]);
        *(float4*)(crow + 4) = make_float4(acc[i][4], acc[i][5], acc[i][6], acc[i][7]);
    }
}

// ---------------------------------------------------------------------------
// RoPE in-place on Q (heads 0..31) and K (heads 32..39) of qkv rows.
// Q and K are contiguous: first 40*128 floats of each row.
// ---------------------------------------------------------------------------
__global__ void rope_kernel(float* __restrict__ qkv, const int* __restrict__ positions)
{
    int idx = blockIdx.x * blockDim.x + threadIdx.x;
    const int TOTAL = SEQ * (NH + NKV) * (HD / 2);
    if (idx >= TOTAL) return;

    int d = idx & 63;                      // pair index 0..63
    int h = (idx >> 6) % (NH + NKV);       // 0..39
    int s = idx / ((NH + NKV) * 64);

    float pos = (float)positions[s];
    // inv_freq = theta^(-2d/HD)
    float inv = powf(10000.0f, -(2.0f * (float)d) / (float)HD);
    float ang = pos * inv;
    float c, sn;
    sincosf(ang, &sn, &c);

    float* base = qkv + (size_t)s * QKVN + h * HD;
    float x1 = base[d];
    float x2 = base[d + 64];
    base[d]      = x1 * c - x2 * sn;
    base[d + 64] = x2 * c + x1 * sn;
}

// ---------------------------------------------------------------------------
// Flash attention, fp32, causal, GQA. Br=Bc=64, 256 threads (8 warps).
// Each warp owns 8 query rows; each lane owns 4 head dims.
// Smem rows padded to HD+4 = 132 floats for conflict-free LDS.128.
// ---------------------------------------------------------------------------
#define BR 64
#define BC 64
#define HDP (HD + 4)   // 132

__global__ __launch_bounds__(256, 1)
void flash_attn_kernel(const float* __restrict__ qkv, float* __restrict__ out)
{
    extern __shared__ float sm[];
    float* Qs = sm;                    // BR * HDP
    float* Ks = Qs + BR * HDP;         // BC * HDP
    float* Vs = Ks + BC * HDP;         // BC * HDP
    float* Ss = Vs + BC * HDP;         // BR * BC

    int qb = blockIdx.x;
    int h  = blockIdx.y;
    int kvh = h / GRP;

    int tid = threadIdx.x;
    int warp = tid >> 5, lane = tid & 31;
    int row0 = warp * 8;

    const float scale = 0.088388347648318447f;  // 1/sqrt(128)

    // Load Q tile (scaled)
    const float* qptr = qkv + (size_t)(qb * BR) * QKVN + h * HD;
    for (int i = tid; i < BR * HD / 4; i += 256) {
        int r = i >> 5;            // 0..63 (HD/4 = 32 float4 per row)
        int c4 = (i & 31) * 4;
        float4 v = *(const float4*)(qptr + (size_t)r * QKVN + c4);
        v.x *= scale; v.y *= scale; v.z *= scale; v.w *= scale;
        *(float4*)&Qs[r * HDP + c4] = v;
    }

    float m_i[8], l_i[8], accv[8][4];
#pragma unroll
    for (int r = 0; r < 8; r++) {
        m_i[r] = -1e30f;
        l_i[r] = 0.f;
#pragma unroll
        for (int d = 0; d < 4; d++) accv[r][d] = 0.f;
    }

    for (int kb = 0; kb <= qb; ++kb) {
        __syncthreads();  // protect K/V/Ss from previous iteration readers

        // Load K and V tiles
        const float* kptr = qkv + (size_t)(kb * BC) * QKVN + NH * HD + kvh * HD;
        const float* vptr = kptr + NKV * HD;
        for (int i = tid; i < BC * HD / 4; i += 256) {
            int r = i >> 5;
            int c4 = (i & 31) * 4;
            *(float4*)&Ks[r * HDP + c4] = *(const float4*)(kptr + (size_t)r * QKVN + c4);
            *(float4*)&Vs[r * HDP + c4] = *(const float4*)(vptr + (size_t)r * QKVN + c4);
        }
        __syncthreads();

        // Scores: Ss[r][c] = Qs[r] . Ks[c]  (+ causal mask on diagonal block)
        bool diag = (kb == qb);
        for (int i = tid; i < BR * BC; i += 256) {
            int r = i >> 6, c = i & 63;
            const float* qrow = Qs + r * HDP;
            const float* krow = Ks + c * HDP;
            float s = 0.f;
#pragma unroll
            for (int d = 0; d < HD; d += 4) {
                float4 q4 = *(const float4*)(qrow + d);
                float4 k4 = *(const float4*)(krow + d);
                s += q4.x * k4.x + q4.y * k4.y + q4.z * k4.z + q4.w * k4.w;
            }
            if (diag && c > r) s = -1e30f;
            Ss[i] = s;
        }
        __syncthreads();

        // Online softmax per owned row + PV accumulate
#pragma unroll
        for (int rr = 0; rr < 8; rr++) {
            int r = row0 + rr;
            float s0 = Ss[r * BC + lane];
            float s1 = Ss[r * BC + lane + 32];
            float mx = fmaxf(s0, s1);
#pragma unroll
            for (int o = 16; o > 0; o >>= 1)
                mx = fmaxf(mx, __shfl_xor_sync(0xFFFFFFFFu, mx, o));
            float m_new = fmaxf(m_i[rr], mx);
            float p0 = __expf(s0 - m_new);
            float p1 = __expf(s1 - m_new);
            Ss[r * BC + lane]      = p0;
            Ss[r * BC + lane + 32] = p1;
            float sum = p0 + p1;
#pragma unroll
            for (int o = 16; o > 0; o >>= 1)
                sum += __shfl_xor_sync(0xFFFFFFFFu, sum, o);
            float corr = __expf(m_i[rr] - m_new);
            l_i[rr] = l_i[rr] * corr + sum;
            m_i[rr] = m_new;
#pragma unroll
            for (int d = 0; d < 4; d++) accv[rr][d] *= corr;
        }
        // (no sync needed: each warp reads back only its own Ss rows)

        // PV: acc[r][lane*4..+3] += sum_c p[r][c] * Vs[c][lane*4..+3]
#pragma unroll
        for (int rr = 0; rr < 8; rr++) {
            int r = row0 + rr;
            float a0 = 0.f, a1 = 0.f, a2 = 0.f, a3 = 0.f;
#pragma unroll 8
            for (int c = 0; c < BC; c++) {
                float p = Ss[r * BC + c];
                float4 v4 = *(const float4*)(Vs + c * HDP + lane * 4);
                a0 += p * v4.x; a1 += p * v4.y; a2 += p * v4.z; a3 += p * v4.w;
            }
            accv[rr][0] += a0; accv[rr][1] += a1;
            accv[rr][2] += a2; accv[rr][3] += a3;
        }
    }

    // Epilogue: normalize and write [S, NH*HD]
#pragma unroll
    for (int rr = 0; rr < 8; rr++) {
        int r = row0 + rr;
        float inv = 1.f / l_i[rr];
        float* orow = out + (size_t)(qb * BR + r) * ATTN_N + h * HD + lane * 4;
        *(float4*)orow = make_float4(accv[rr][0] * inv, accv[rr][1] * inv,
                                     accv[rr][2] * inv, accv[rr][3] * inv);
    }
}

// ---------------------------------------------------------------------------
// kernel_launch
// ---------------------------------------------------------------------------
extern "C" void kernel_launch(void* const* d_in, const int* in_sizes, int n_in,
                              void* d_out, int out_size)
{
    const float* hs    = (const float*)d_in[0];  // [1, 2048, 4096]
    const int*   pos   = (const int*)d_in[1];    // [1, 2048]
    const float* w_qkv = (const float*)d_in[2];  // [4096, 6144]
    const float* w_o   = (const float*)d_in[3];  // [4096, 4096]
    float* out = (float*)d_out;                  // [1, 2048, 4096]

    float* qkv;  cudaGetSymbolAddress((void**)&qkv,  g_qkv);
    float* attn; cudaGetSymbolAddress((void**)&attn, g_attn);

    // 1) QKV projection: [2048,4096] x [4096,6144] -> [2048,6144]
    sgemm_kernel<<<dim3(QKVN / 128, SEQ / 128), 256>>>(hs, w_qkv, qkv, SEQ, QKVN, HID);

    // 2) RoPE in-place on Q and K
    {
        int total = SEQ * (NH + NKV) * (HD / 2);
        rope_kernel<<<(total + 255) / 256, 256>>>(qkv, pos);
    }

    // 3) Flash attention -> [2048, 4096]
    {
        size_t smem = (size_t)(BR * HDP + 2 * BC * HDP + BR * BC) * sizeof(float);
        cudaFuncSetAttribute(flash_attn_kernel,
                             cudaFuncAttributeMaxDynamicSharedMemorySize, (int)smem);
        flash_attn_kernel<<<dim3(SEQ / BR, NH), 256, smem>>>(qkv, attn);
    }

    // 4) Output projection: [2048,4096] x [4096,4096] -> [2048,4096]
    sgemm_kernel<<<dim3(HID / 128, SEQ / 128), 256>>>(attn, w_o, out, SEQ, HID, HID);
}

// round 4
// speedup vs baseline: 1.6612x; 1.6612x over previous
#include <cuda_runtime.h>
#include <cuda_bf16.h>
#include <stdint.h>
#include <math.h>

#define SEQ   2048
#define HID   4096
#define NH    32
#define NKV   8
#define HD    128
#define GRP   (NH / NKV)             // 4
#define QKVN  ((NH + 2 * NKV) * HD)  // 6144
#define ATTN_N (NH * HD)             // 4096

// ---------------------------------------------------------------------------
// Scratch (device globals; no allocations allowed)
// ---------------------------------------------------------------------------
__device__ float g_qkv[SEQ * QKVN];          // QKV output, fp32
__device__ float g_attn[SEQ * ATTN_N];       // attention output, fp32
__device__ __nv_bfloat16 g_Ah[SEQ * HID];    // A hi  (hs / attn)
__device__ __nv_bfloat16 g_Al[SEQ * HID];    // A lo
__device__ __nv_bfloat16 g_Bh[QKVN * HID];   // B^T hi (w_qkv^T / w_o^T)
__device__ __nv_bfloat16 g_Bl[QKVN * HID];   // B^T lo

// ---------------------------------------------------------------------------
// PTX helpers (portable: no 'a'-suffix features)
// ---------------------------------------------------------------------------
__device__ __forceinline__ uint32_t s2u(const void* p) {
    uint32_t a;
    asm("{ .reg .u64 t; cvta.to.shared.u64 t, %1; cvt.u32.u64 %0, t; }"
        : "=r"(a) : "l"(p));
    return a;
}

__device__ __forceinline__ void cpa16(uint32_t s, const void* g) {
    asm volatile("cp.async.cg.shared.global [%0], [%1], 16;" :: "r"(s), "l"(g));
}
__device__ __forceinline__ void cpa_commit() {
    asm volatile("cp.async.commit_group;" ::: "memory");
}
template <int N>
__device__ __forceinline__ void cpa_wait() {
    asm volatile("cp.async.wait_group %0;" :: "n"(N) : "memory");
}

__device__ __forceinline__ void ldm_x4(uint32_t* r, uint32_t addr) {
    asm volatile("ldmatrix.sync.aligned.m8n8.x4.shared.b16 {%0,%1,%2,%3}, [%4];"
                 : "=r"(r[0]), "=r"(r[1]), "=r"(r[2]), "=r"(r[3]) : "r"(addr));
}
__device__ __forceinline__ void ldm_x2(uint32_t* r, uint32_t addr) {
    asm volatile("ldmatrix.sync.aligned.m8n8.x2.shared.b16 {%0,%1}, [%2];"
                 : "=r"(r[0]), "=r"(r[1]) : "r"(addr));
}

__device__ __forceinline__ void mma16816(float* c, const uint32_t* a, const uint32_t* b) {
    asm volatile(
        "mma.sync.aligned.m16n8k16.row.col.f32.bf16.bf16.f32 "
        "{%0,%1,%2,%3}, {%4,%5,%6,%7}, {%8,%9}, {%0,%1,%2,%3};"
        : "+f"(c[0]), "+f"(c[1]), "+f"(c[2]), "+f"(c[3])
        : "r"(a[0]), "r"(a[1]), "r"(a[2]), "r"(a[3]), "r"(b[0]), "r"(b[1]));
}

// ---------------------------------------------------------------------------
// Split fp32 -> bf16 hi + lo (elementwise, float4)
// ---------------------------------------------------------------------------
__global__ void split_kernel(const float* __restrict__ in,
                             __nv_bfloat16* __restrict__ hi,
                             __nv_bfloat16* __restrict__ lo, int n4)
{
    int i = blockIdx.x * blockDim.x + threadIdx.x;
    if (i >= n4) return;
    float4 v = ((const float4*)in)[i];
    __nv_bfloat16 h0 = __float2bfloat16(v.x);
    __nv_bfloat16 h1 = __float2bfloat16(v.y);
    __nv_bfloat16 h2 = __float2bfloat16(v.z);
    __nv_bfloat16 h3 = __float2bfloat16(v.w);
    __nv_bfloat16 l0 = __float2bfloat16(v.x - __bfloat162float(h0));
    __nv_bfloat16 l1 = __float2bfloat16(v.y - __bfloat162float(h1));
    __nv_bfloat16 l2 = __float2bfloat16(v.z - __bfloat162float(h2));
    __nv_bfloat16 l3 = __float2bfloat16(v.w - __bfloat162float(h3));
    __nv_bfloat162* hp = (__nv_bfloat162*)hi;
    __nv_bfloat162* lp = (__nv_bfloat162*)lo;
    hp[2 * i]     = __nv_bfloat162(h0, h1);
    hp[2 * i + 1] = __nv_bfloat162(h2, h3);
    lp[2 * i]     = __nv_bfloat162(l0, l1);
    lp[2 * i + 1] = __nv_bfloat162(l2, l3);
}

// ---------------------------------------------------------------------------
// Transpose + split: in fp32 [K,N] row-major -> hi/lo bf16 [N,K]
// ---------------------------------------------------------------------------
__global__ void splitT_kernel(const float* __restrict__ in,
                              __nv_bfloat16* __restrict__ hi,
                              __nv_bfloat16* __restrict__ lo, int K, int N)
{
    __shared__ float t[32][33];
    int n0 = blockIdx.x * 32, k0 = blockIdx.y * 32;
    int tx = threadIdx.x, ty = threadIdx.y;   // 32 x 8
#pragma unroll
    for (int j = 0; j < 4; j++)
        t[ty + 8 * j][tx] = in[(size_t)(k0 + ty + 8 * j) * N + n0 + tx];
    __syncthreads();
#pragma unroll
    for (int j = 0; j < 4; j++) {
        float a = t[tx][ty + 8 * j];            // element (k0+tx, n0+ty+8j)
        size_t o = (size_t)(n0 + ty + 8 * j) * K + k0 + tx;
        __nv_bfloat16 h = __float2bfloat16(a);
        hi[o] = h;
        lo[o] = __float2bfloat16(a - __bfloat162float(h));
    }
}

// ---------------------------------------------------------------------------
// mma.sync GEMM: C[M,Nc] = A[M,K] * B[K,Nc], fp32-emulated via bf16x3.
// A as hi/lo bf16 [M,K]; B transposed as hi/lo bf16 [Nc,K].
// CTA 128x128, KC=64, 2-stage cp.async pipeline, 8 warps (warp tile 64x32).
// Smem pitch 144B (128+16) -> conflict-free ldmatrix without swizzle.
// ---------------------------------------------------------------------------
#define KC      64
#define PITCH_B 144                       // bytes per 64-bf16 row in smem
#define TILE_SB (128 * PITCH_B)           // 18432 bytes per tile
#define STAGE_B (4 * TILE_SB)             // 73728 bytes (Ah,Al,Bh,Bl)
#define GEMM_SMEM (2 * STAGE_B)           // 147456

__global__ __launch_bounds__(256, 1)
void gemm_mma_kernel(const __nv_bfloat16* __restrict__ Ah,
                     const __nv_bfloat16* __restrict__ Al,
                     const __nv_bfloat16* __restrict__ Bh,
                     const __nv_bfloat16* __restrict__ Bl,
                     float* __restrict__ C, int K, int Nc)
{
    extern __shared__ char smc[];
    const uint32_t sbase = s2u(smc);

    const int tid  = threadIdx.x;
    const int lane = tid & 31;
    const int warp = tid >> 5;
    const int wm = warp >> 2;              // 0..1  (M: 64-row halves)
    const int wn = warp & 3;               // 0..3  (N: 32-col quarters)
    const int bm = blockIdx.y, bn = blockIdx.x;
    const int nchunk = K / KC;

    const __nv_bfloat16* gsrc[4] = {Ah, Al, Bh, Bl};
    const int row0[4] = {bm * 128, bm * 128, bn * 128, bn * 128};

    // --- stage loader: 4 tiles x 128 rows x 8 sixteen-byte chunks ---
    auto load_stage = [&](int c, int s) {
        uint32_t stg = sbase + s * STAGE_B;
        int kt = c * KC;
#pragma unroll
        for (int j = 0; j < 16; ++j) {
            int idx  = tid + j * 256;          // 0..4095
            int tsel = idx >> 10;              // 0..3
            int w    = idx & 1023;
            int r    = w >> 3;                 // 0..127
            int ck   = w & 7;                  // 0..7 (16B chunk within row)
            cpa16(stg + tsel * TILE_SB + r * PITCH_B + ck * 16,
                  gsrc[tsel] + (size_t)(row0[tsel] + r) * K + kt + ck * 8);
        }
    };

    float acc[4][4][4];
#pragma unroll
    for (int i = 0; i < 4; i++)
#pragma unroll
        for (int j = 0; j < 4; j++)
#pragma unroll
            for (int q = 0; q < 4; q++) acc[i][j][q] = 0.f;

    load_stage(0, 0);
    cpa_commit();

    for (int c = 0; c < nchunk; ++c) {
        if (c + 1 < nchunk) {
            load_stage(c + 1, (c + 1) & 1);
            cpa_commit();
            cpa_wait<1>();
        } else {
            cpa_wait<0>();
        }
        __syncthreads();

        uint32_t stg = sbase + (c & 1) * STAGE_B;
        uint32_t aBaseH = stg + (wm * 64 + (lane & 15)) * PITCH_B + (lane >> 4) * 16;
        uint32_t aBaseL = aBaseH + TILE_SB;
        uint32_t bBaseH = stg + 2 * TILE_SB +
                          (wn * 32 + (lane & 7)) * PITCH_B + ((lane >> 3) & 1) * 16;
        uint32_t bBaseL = bBaseH + TILE_SB;

#pragma unroll
        for (int s = 0; s < 4; ++s) {      // k16 steps within KC=64
            uint32_t ah[4][4], al[4][4], bh[4][2], bl[4][2];
#pragma unroll
            for (int i = 0; i < 4; ++i) {
                ldm_x4(ah[i], aBaseH + i * 16 * PITCH_B + s * 32);
                ldm_x4(al[i], aBaseL + i * 16 * PITCH_B + s * 32);
            }
#pragma unroll
            for (int j = 0; j < 4; ++j) {
                ldm_x2(bh[j], bBaseH + j * 8 * PITCH_B + s * 32);
                ldm_x2(bl[j], bBaseL + j * 8 * PITCH_B + s * 32);
            }
#pragma unroll
            for (int i = 0; i < 4; ++i)
#pragma unroll
                for (int j = 0; j < 4; ++j) {
                    mma16816(acc[i][j], ah[i], bh[j]);
                    mma16816(acc[i][j], ah[i], bl[j]);
                    mma16816(acc[i][j], al[i], bh[j]);
                }
        }
        __syncthreads();
    }

    // --- epilogue: fragment layout m16n8 f32 ---
    const int rbase = bm * 128 + wm * 64 + (lane >> 2);
    const int cbase = bn * 128 + wn * 32 + (lane & 3) * 2;
#pragma unroll
    for (int i = 0; i < 4; ++i) {
#pragma unroll
        for (int j = 0; j < 4; ++j) {
            int r = rbase + i * 16;
            int col = cbase + j * 8;
            *(float2*)&C[(size_t)r * Nc + col] =
                make_float2(acc[i][j][0], acc[i][j][1]);
            *(float2*)&C[(size_t)(r + 8) * Nc + col] =
                make_float2(acc[i][j][2], acc[i][j][3]);
        }
    }
}

// ---------------------------------------------------------------------------
// RoPE in-place on Q (heads 0..31) and K (heads 32..39) of qkv rows.
// ---------------------------------------------------------------------------
__global__ void rope_kernel(float* __restrict__ qkv, const int* __restrict__ positions)
{
    int idx = blockIdx.x * blockDim.x + threadIdx.x;
    const int TOTAL = SEQ * (NH + NKV) * (HD / 2);
    if (idx >= TOTAL) return;

    int d = idx & 63;
    int h = (idx >> 6) % (NH + NKV);
    int s = idx / ((NH + NKV) * 64);

    float pos = (float)positions[s];
    float inv = powf(10000.0f, -(2.0f * (float)d) / (float)HD);
    float ang = pos * inv;
    float c, sn;
    sincosf(ang, &sn, &c);

    float* base = qkv + (size_t)s * QKVN + h * HD;
    float x1 = base[d];
    float x2 = base[d + 64];
    base[d]      = x1 * c - x2 * sn;
    base[d + 64] = x2 * c + x1 * sn;
}

// ---------------------------------------------------------------------------
// Flash attention, fp32, causal, GQA. Br=Bc=64, 256 threads.
// ---------------------------------------------------------------------------
#define BR 64
#define BC 64
#define HDP (HD + 4)

__global__ __launch_bounds__(256, 1)
void flash_attn_kernel(const float* __restrict__ qkv, float* __restrict__ out)
{
    extern __shared__ float smf[];
    float* Qs = smf;
    float* Ks = Qs + BR * HDP;
    float* Vs = Ks + BC * HDP;
    float* Ss = Vs + BC * HDP;

    int qb = blockIdx.x;
    int h  = blockIdx.y;
    int kvh = h / GRP;

    int tid = threadIdx.x;
    int warp = tid >> 5, lane = tid & 31;
    int row0 = warp * 8;

    const float scale = 0.088388347648318447f;

    const float* qptr = qkv + (size_t)(qb * BR) * QKVN + h * HD;
    for (int i = tid; i < BR * HD / 4; i += 256) {
        int r = i >> 5;
        int c4 = (i & 31) * 4;
        float4 v = *(const float4*)(qptr + (size_t)r * QKVN + c4);
        v.x *= scale; v.y *= scale; v.z *= scale; v.w *= scale;
        *(float4*)&Qs[r * HDP + c4] = v;
    }

    float m_i[8], l_i[8], accv[8][4];
#pragma unroll
    for (int r = 0; r < 8; r++) {
        m_i[r] = -1e30f;
        l_i[r] = 0.f;
#pragma unroll
        for (int d = 0; d < 4; d++) accv[r][d] = 0.f;
    }

    for (int kb = 0; kb <= qb; ++kb) {
        __syncthreads();

        const float* kptr = qkv + (size_t)(kb * BC) * QKVN + NH * HD + kvh * HD;
        const float* vptr = kptr + NKV * HD;
        for (int i = tid; i < BC * HD / 4; i += 256) {
            int r = i >> 5;
            int c4 = (i & 31) * 4;
            *(float4*)&Ks[r * HDP + c4] = *(const float4*)(kptr + (size_t)r * QKVN + c4);
            *(float4*)&Vs[r * HDP + c4] = *(const float4*)(vptr + (size_t)r * QKVN + c4);
        }
        __syncthreads();

        bool diag = (kb == qb);
        for (int i = tid; i < BR * BC; i += 256) {
            int r = i >> 6, c = i & 63;
            const float* qrow = Qs + r * HDP;
            const float* krow = Ks + c * HDP;
            float s = 0.f;
#pragma unroll
            for (int d = 0; d < HD; d += 4) {
                float4 q4 = *(const float4*)(qrow + d);
                float4 k4 = *(const float4*)(krow + d);
                s += q4.x * k4.x + q4.y * k4.y + q4.z * k4.z + q4.w * k4.w;
            }
            if (diag && c > r) s = -1e30f;
            Ss[i] = s;
        }
        __syncthreads();

#pragma unroll
        for (int rr = 0; rr < 8; rr++) {
            int r = row0 + rr;
            float s0 = Ss[r * BC + lane];
            float s1 = Ss[r * BC + lane + 32];
            float mx = fmaxf(s0, s1);
#pragma unroll
            for (int o = 16; o > 0; o >>= 1)
                mx = fmaxf(mx, __shfl_xor_sync(0xFFFFFFFFu, mx, o));
            float m_new = fmaxf(m_i[rr], mx);
            float p0 = __expf(s0 - m_new);
            float p1 = __expf(s1 - m_new);
            Ss[r * BC + lane]      = p0;
            Ss[r * BC + lane + 32] = p1;
            float sum = p0 + p1;
#pragma unroll
            for (int o = 16; o > 0; o >>= 1)
                sum += __shfl_xor_sync(0xFFFFFFFFu, sum, o);
            float corr = __expf(m_i[rr] - m_new);
            l_i[rr] = l_i[rr] * corr + sum;
            m_i[rr] = m_new;
#pragma unroll
            for (int d = 0; d < 4; d++) accv[rr][d] *= corr;
        }

#pragma unroll
        for (int rr = 0; rr < 8; rr++) {
            int r = row0 + rr;
            float a0 = 0.f, a1 = 0.f, a2 = 0.f, a3 = 0.f;
#pragma unroll 8
            for (int c = 0; c < BC; c++) {
                float p = Ss[r * BC + c];
                float4 v4 = *(const float4*)(Vs + c * HDP + lane * 4);
                a0 += p * v4.x; a1 += p * v4.y; a2 += p * v4.z; a3 += p * v4.w;
            }
            accv[rr][0] += a0; accv[rr][1] += a1;
            accv[rr][2] += a2; accv[rr][3] += a3;
        }
    }

#pragma unroll
    for (int rr = 0; rr < 8; rr++) {
        int r = row0 + rr;
        float inv = 1.f / l_i[rr];
        float* orow = out + (size_t)(qb * BR + r) * ATTN_N + h * HD + lane * 4;
        *(float4*)orow = make_float4(accv[rr][0] * inv, accv[rr][1] * inv,
                                     accv[rr][2] * inv, accv[rr][3] * inv);
    }
}

// ---------------------------------------------------------------------------
// kernel_launch
// ---------------------------------------------------------------------------
extern "C" void kernel_launch(void* const* d_in, const int* in_sizes, int n_in,
                              void* d_out, int out_size)
{
    const float* hs    = (const float*)d_in[0];
    const int*   pos   = (const int*)d_in[1];
    const float* w_qkv = (const float*)d_in[2];
    const float* w_o   = (const float*)d_in[3];
    float* out = (float*)d_out;

    float* qkv;  cudaGetSymbolAddress((void**)&qkv,  g_qkv);
    float* attn; cudaGetSymbolAddress((void**)&attn, g_attn);
    __nv_bfloat16 *Ah, *Al, *Bh, *Bl;
    cudaGetSymbolAddress((void**)&Ah, g_Ah);
    cudaGetSymbolAddress((void**)&Al, g_Al);
    cudaGetSymbolAddress((void**)&Bh, g_Bh);
    cudaGetSymbolAddress((void**)&Bl, g_Bl);

    cudaFuncSetAttribute(gemm_mma_kernel,
                         cudaFuncAttributeMaxDynamicSharedMemorySize, GEMM_SMEM);

    // 1) split hs -> Ah/Al ; transpose+split w_qkv -> Bh/Bl
    split_kernel<<<(SEQ * HID / 4 + 255) / 256, 256>>>(hs, Ah, Al, SEQ * HID / 4);
    splitT_kernel<<<dim3(QKVN / 32, HID / 32), dim3(32, 8)>>>(w_qkv, Bh, Bl, HID, QKVN);

    // 2) QKV projection on tensor cores (mma.sync): [2048,4096] x [4096,6144]
    gemm_mma_kernel<<<dim3(QKVN / 128, SEQ / 128), 256, GEMM_SMEM>>>(
        Ah, Al, Bh, Bl, qkv, HID, QKVN);

    // 3) RoPE in-place
    {
        int total = SEQ * (NH + NKV) * (HD / 2);
        rope_kernel<<<(total + 255) / 256, 256>>>(qkv, pos);
    }

    // 4) Flash attention
    {
        size_t smem = (size_t)(BR * HDP + 2 * BC * HDP + BR * BC) * sizeof(float);
        cudaFuncSetAttribute(flash_attn_kernel,
                             cudaFuncAttributeMaxDynamicSharedMemorySize, (int)smem);
        flash_attn_kernel<<<dim3(SEQ / BR, NH), 256, smem>>>(qkv, attn);
    }

    // 5) split attn -> Ah/Al ; transpose+split w_o -> Bh/Bl
    split_kernel<<<(SEQ * HID / 4 + 255) / 256, 256>>>(attn, Ah, Al, SEQ * HID / 4);
    splitT_kernel<<<dim3(HID / 32, HID / 32), dim3(32, 8)>>>(w_o, Bh, Bl, HID, HID);

    // 6) Output projection on tensor cores (mma.sync): [2048,4096] x [4096,4096]
    gemm_mma_kernel<<<dim3(HID / 128, SEQ / 128), 256, GEMM_SMEM>>>(
        Ah, Al, Bh, Bl, out, HID, HID);
}

// round 5
// speedup vs baseline: 2.8240x; 1.7000x over previous
#include <cuda_runtime.h>
#include <cuda_bf16.h>
#include <stdint.h>
#include <math.h>

#define SEQ   2048
#define HID   4096
#define NH    32
#define NKV   8
#define HD    128
#define GRP   (NH / NKV)             // 4
#define QKVN  ((NH + 2 * NKV) * HD)  // 6144
#define ATTN_N (NH * HD)             // 4096

// ---------------------------------------------------------------------------
// Scratch (device globals; no allocations allowed)
// ---------------------------------------------------------------------------
__device__ float g_qkv[SEQ * QKVN];            // QKV output, fp32
__device__ __nv_bfloat16 g_Ah[SEQ * HID];      // GEMM A hi (hs / attn-out)
__device__ __nv_bfloat16 g_Al[SEQ * HID];      // GEMM A lo
__device__ __nv_bfloat16 g_Bh[QKVN * HID];     // B^T hi
__device__ __nv_bfloat16 g_Bl[QKVN * HID];     // B^T lo
__device__ __nv_bfloat16 g_Qh[NH * SEQ * HD];  // roped Q hi  [h][s][d]
__device__ __nv_bfloat16 g_Ql[NH * SEQ * HD];
__device__ __nv_bfloat16 g_Kh[NKV * SEQ * HD]; // roped K hi  [h][s][d]
__device__ __nv_bfloat16 g_Kl[NKV * SEQ * HD];
__device__ __nv_bfloat16 g_Vh[NKV * SEQ * HD]; // V hi        [h][s][d]
__device__ __nv_bfloat16 g_Vl[NKV * SEQ * HD];

// ---------------------------------------------------------------------------
// PTX helpers (portable: no 'a'-suffix features)
// ---------------------------------------------------------------------------
__device__ __forceinline__ uint32_t s2u(const void* p) {
    uint32_t a;
    asm("{ .reg .u64 t; cvta.to.shared.u64 t, %1; cvt.u32.u64 %0, t; }"
        : "=r"(a) : "l"(p));
    return a;
}

__device__ __forceinline__ void cpa16(uint32_t s, const void* g) {
    asm volatile("cp.async.cg.shared.global [%0], [%1], 16;" :: "r"(s), "l"(g));
}
__device__ __forceinline__ void cpa_commit() {
    asm volatile("cp.async.commit_group;" ::: "memory");
}
template <int N>
__device__ __forceinline__ void cpa_wait() {
    asm volatile("cp.async.wait_group %0;" :: "n"(N) : "memory");
}

__device__ __forceinline__ void ldm_x4(uint32_t* r, uint32_t addr) {
    asm volatile("ldmatrix.sync.aligned.m8n8.x4.shared.b16 {%0,%1,%2,%3}, [%4];"
                 : "=r"(r[0]), "=r"(r[1]), "=r"(r[2]), "=r"(r[3]) : "r"(addr));
}
__device__ __forceinline__ void ldm_x2(uint32_t* r, uint32_t addr) {
    asm volatile("ldmatrix.sync.aligned.m8n8.x2.shared.b16 {%0,%1}, [%2];"
                 : "=r"(r[0]), "=r"(r[1]) : "r"(addr));
}
__device__ __forceinline__ void ldm_x2t(uint32_t* r, uint32_t addr) {
    asm volatile("ldmatrix.sync.aligned.m8n8.x2.trans.shared.b16 {%0,%1}, [%2];"
                 : "=r"(r[0]), "=r"(r[1]) : "r"(addr));
}

__device__ __forceinline__ void mma16816(float* c, const uint32_t* a, const uint32_t* b) {
    asm volatile(
        "mma.sync.aligned.m16n8k16.row.col.f32.bf16.bf16.f32 "
        "{%0,%1,%2,%3}, {%4,%5,%6,%7}, {%8,%9}, {%0,%1,%2,%3};"
        : "+f"(c[0]), "+f"(c[1]), "+f"(c[2]), "+f"(c[3])
        : "r"(a[0]), "r"(a[1]), "r"(a[2]), "r"(a[3]), "r"(b[0]), "r"(b[1]));
}

// ---------------------------------------------------------------------------
// Split fp32 -> bf16 hi + lo (elementwise, float4)
// ---------------------------------------------------------------------------
__global__ void split_kernel(const float* __restrict__ in,
                             __nv_bfloat16* __restrict__ hi,
                             __nv_bfloat16* __restrict__ lo, int n4)
{
    int i = blockIdx.x * blockDim.x + threadIdx.x;
    if (i >= n4) return;
    float4 v = ((const float4*)in)[i];
    __nv_bfloat16 h0 = __float2bfloat16(v.x);
    __nv_bfloat16 h1 = __float2bfloat16(v.y);
    __nv_bfloat16 h2 = __float2bfloat16(v.z);
    __nv_bfloat16 h3 = __float2bfloat16(v.w);
    __nv_bfloat16 l0 = __float2bfloat16(v.x - __bfloat162float(h0));
    __nv_bfloat16 l1 = __float2bfloat16(v.y - __bfloat162float(h1));
    __nv_bfloat16 l2 = __float2bfloat16(v.z - __bfloat162float(h2));
    __nv_bfloat16 l3 = __float2bfloat16(v.w - __bfloat162float(h3));
    __nv_bfloat162* hp = (__nv_bfloat162*)hi;
    __nv_bfloat162* lp = (__nv_bfloat162*)lo;
    hp[2 * i]     = __nv_bfloat162(h0, h1);
    hp[2 * i + 1] = __nv_bfloat162(h2, h3);
    lp[2 * i]     = __nv_bfloat162(l0, l1);
    lp[2 * i + 1] = __nv_bfloat162(l2, l3);
}

// ---------------------------------------------------------------------------
// Transpose + split: in fp32 [K,N] row-major -> hi/lo bf16 [N,K]
// ---------------------------------------------------------------------------
__global__ void splitT_kernel(const float* __restrict__ in,
                              __nv_bfloat16* __restrict__ hi,
                              __nv_bfloat16* __restrict__ lo, int K, int N)
{
    __shared__ float t[32][33];
    int n0 = blockIdx.x * 32, k0 = blockIdx.y * 32;
    int tx = threadIdx.x, ty = threadIdx.y;   // 32 x 8
#pragma unroll
    for (int j = 0; j < 4; j++)
        t[ty + 8 * j][tx] = in[(size_t)(k0 + ty + 8 * j) * N + n0 + tx];
    __syncthreads();
#pragma unroll
    for (int j = 0; j < 4; j++) {
        float a = t[tx][ty + 8 * j];
        size_t o = (size_t)(n0 + ty + 8 * j) * K + k0 + tx;
        __nv_bfloat16 h = __float2bfloat16(a);
        hi[o] = h;
        lo[o] = __float2bfloat16(a - __bfloat162float(h));
    }
}

// ---------------------------------------------------------------------------
// mma.sync GEMM (unchanged from validated round-4 kernel)
// ---------------------------------------------------------------------------
#define KC      64
#define PITCH_B 144
#define TILE_SB (128 * PITCH_B)
#define STAGE_B (4 * TILE_SB)
#define GEMM_SMEM (2 * STAGE_B)

__global__ __launch_bounds__(256, 1)
void gemm_mma_kernel(const __nv_bfloat16* __restrict__ Ah,
                     const __nv_bfloat16* __restrict__ Al,
                     const __nv_bfloat16* __restrict__ Bh,
                     const __nv_bfloat16* __restrict__ Bl,
                     float* __restrict__ C, int K, int Nc)
{
    extern __shared__ char smc[];
    const uint32_t sbase = s2u(smc);

    const int tid  = threadIdx.x;
    const int lane = tid & 31;
    const int warp = tid >> 5;
    const int wm = warp >> 2;
    const int wn = warp & 3;
    const int bm = blockIdx.y, bn = blockIdx.x;
    const int nchunk = K / KC;

    const __nv_bfloat16* gsrc[4] = {Ah, Al, Bh, Bl};
    const int row0[4] = {bm * 128, bm * 128, bn * 128, bn * 128};

    auto load_stage = [&](int c, int s) {
        uint32_t stg = sbase + s * STAGE_B;
        int kt = c * KC;
#pragma unroll
        for (int j = 0; j < 16; ++j) {
            int idx  = tid + j * 256;
            int tsel = idx >> 10;
            int w    = idx & 1023;
            int r    = w >> 3;
            int ck   = w & 7;
            cpa16(stg + tsel * TILE_SB + r * PITCH_B + ck * 16,
                  gsrc[tsel] + (size_t)(row0[tsel] + r) * K + kt + ck * 8);
        }
    };

    float acc[4][4][4];
#pragma unroll
    for (int i = 0; i < 4; i++)
#pragma unroll
        for (int j = 0; j < 4; j++)
#pragma unroll
            for (int q = 0; q < 4; q++) acc[i][j][q] = 0.f;

    load_stage(0, 0);
    cpa_commit();

    for (int c = 0; c < nchunk; ++c) {
        if (c + 1 < nchunk) {
            load_stage(c + 1, (c + 1) & 1);
            cpa_commit();
            cpa_wait<1>();
        } else {
            cpa_wait<0>();
        }
        __syncthreads();

        uint32_t stg = sbase + (c & 1) * STAGE_B;
        uint32_t aBaseH = stg + (wm * 64 + (lane & 15)) * PITCH_B + (lane >> 4) * 16;
        uint32_t aBaseL = aBaseH + TILE_SB;
        uint32_t bBaseH = stg + 2 * TILE_SB +
                          (wn * 32 + (lane & 7)) * PITCH_B + ((lane >> 3) & 1) * 16;
        uint32_t bBaseL = bBaseH + TILE_SB;

#pragma unroll
        for (int s = 0; s < 4; ++s) {
            uint32_t ah[4][4], al[4][4], bh[4][2], bl[4][2];
#pragma unroll
            for (int i = 0; i < 4; ++i) {
                ldm_x4(ah[i], aBaseH + i * 16 * PITCH_B + s * 32);
                ldm_x4(al[i], aBaseL + i * 16 * PITCH_B + s * 32);
            }
#pragma unroll
            for (int j = 0; j < 4; ++j) {
                ldm_x2(bh[j], bBaseH + j * 8 * PITCH_B + s * 32);
                ldm_x2(bl[j], bBaseL + j * 8 * PITCH_B + s * 32);
            }
#pragma unroll
            for (int i = 0; i < 4; ++i)
#pragma unroll
                for (int j = 0; j < 4; ++j) {
                    mma16816(acc[i][j], ah[i], bh[j]);
                    mma16816(acc[i][j], ah[i], bl[j]);
                    mma16816(acc[i][j], al[i], bh[j]);
                }
        }
        __syncthreads();
    }

    const int rbase = bm * 128 + wm * 64 + (lane >> 2);
    const int cbase = bn * 128 + wn * 32 + (lane & 3) * 2;
#pragma unroll
    for (int i = 0; i < 4; ++i) {
#pragma unroll
        for (int j = 0; j < 4; ++j) {
            int r = rbase + i * 16;
            int col = cbase + j * 8;
            *(float2*)&C[(size_t)r * Nc + col] =
                make_float2(acc[i][j][0], acc[i][j][1]);
            *(float2*)&C[(size_t)(r + 8) * Nc + col] =
                make_float2(acc[i][j][2], acc[i][j][3]);
        }
    }
}

// ---------------------------------------------------------------------------
// RoPE + hi/lo split: fp32 qkv -> bf16 hi/lo Q (scaled), K, V in [h][s][d].
// ---------------------------------------------------------------------------
__global__ void rope_split_kernel(const float* __restrict__ qkv,
                                  const int* __restrict__ positions,
                                  __nv_bfloat16* __restrict__ Qh, __nv_bfloat16* __restrict__ Ql,
                                  __nv_bfloat16* __restrict__ Kh, __nv_bfloat16* __restrict__ Kl,
                                  __nv_bfloat16* __restrict__ Vh, __nv_bfloat16* __restrict__ Vl)
{
    int idx = blockIdx.x * blockDim.x + threadIdx.x;
    const int NHTOT = NH + 2 * NKV;  // 48
    const int TOTAL = SEQ * NHTOT * (HD / 2);
    if (idx >= TOTAL) return;

    int d = idx & 63;
    int h = (idx >> 6) % NHTOT;
    int s = idx / (NHTOT * 64);

    const float* base = qkv + (size_t)s * QKVN + h * HD;
    float x1 = base[d];
    float x2 = base[d + 64];
    float y1 = x1, y2 = x2;

    if (h < NH + NKV) {  // rope for Q and K
        float pos = (float)positions[s];
        float inv = powf(10000.0f, -(2.0f * (float)d) / (float)HD);
        float ang = pos * inv;
        float c, sn;
        sincosf(ang, &sn, &c);
        y1 = x1 * c - x2 * sn;
        y2 = x2 * c + x1 * sn;
    }

    __nv_bfloat16 *dh, *dl;
    size_t off;
    if (h < NH) {
        const float scale = 0.088388347648318447f;  // 1/sqrt(128)
        y1 *= scale; y2 *= scale;
        dh = Qh; dl = Ql;
        off = ((size_t)h * SEQ + s) * HD + d;
    } else if (h < NH + NKV) {
        dh = Kh; dl = Kl;
        off = ((size_t)(h - NH) * SEQ + s) * HD + d;
    } else {
        dh = Vh; dl = Vl;
        off = ((size_t)(h - NH - NKV) * SEQ + s) * HD + d;
    }
    __nv_bfloat16 h1 = __float2bfloat16(y1);
    __nv_bfloat16 h2 = __float2bfloat16(y2);
    dh[off]      = h1;
    dh[off + 64] = h2;
    dl[off]      = __float2bfloat16(y1 - __bfloat162float(h1));
    dl[off + 64] = __float2bfloat16(y2 - __bfloat162float(h2));
}

// ---------------------------------------------------------------------------
// Tensor-core flash attention (bf16x3), causal, GQA. Br=Bc=64, 256 threads.
// Writes output directly as bf16 hi/lo into the GEMM A buffers.
// ---------------------------------------------------------------------------
#define APITCH 272                      // 128 bf16 + 16B pad
#define PPITCH 144                      // 64 bf16 + 16B pad
#define SSP    68                       // Ss row pitch (floats)
#define ATILE  (64 * APITCH)            // 17408
#define O_QH   0
#define O_QL   (O_QH + ATILE)
#define O_KH   (O_QL + ATILE)
#define O_KL   (O_KH + ATILE)
#define O_VH   (O_KL + ATILE)
#define O_VL   (O_VH + ATILE)
#define O_SS   (O_VL + ATILE)           // 104448
#define O_PH   (O_SS + 64 * SSP * 4)    // 121856
#define O_PL   (O_PH + 64 * PPITCH)
#define O_CORR (O_PL + 64 * PPITCH)     // 140288
#define O_LINV (O_CORR + 256)
#define FL_SMEM (O_LINV + 256)          // 140800

__global__ __launch_bounds__(256, 1)
void flash_mma_kernel(const __nv_bfloat16* __restrict__ Qh, const __nv_bfloat16* __restrict__ Ql,
                      const __nv_bfloat16* __restrict__ Kh, const __nv_bfloat16* __restrict__ Kl,
                      const __nv_bfloat16* __restrict__ Vh, const __nv_bfloat16* __restrict__ Vl,
                      __nv_bfloat16* __restrict__ outH, __nv_bfloat16* __restrict__ outL)
{
    extern __shared__ char smx[];
    const uint32_t sb = s2u(smx);
    float* SsF  = (float*)(smx + O_SS);
    float* corr = (float*)(smx + O_CORR);
    float* linv = (float*)(smx + O_LINV);

    const int qb = (int)gridDim.x - 1 - (int)blockIdx.x;  // longest first
    const int h  = blockIdx.y;
    const int kvh = h / GRP;

    const int tid  = threadIdx.x;
    const int warp = tid >> 5;
    const int lane = tid & 31;
    const int wr = warp & 3;            // 16-row group (both phases)
    const int wc = warp >> 2;           // col group: QK n32, PV n64

    // --- load Q tiles (hi/lo) ---
    {
        const __nv_bfloat16* qH = Qh + ((size_t)h * SEQ + qb * 64) * HD;
        const __nv_bfloat16* qL = Ql + ((size_t)h * SEQ + qb * 64) * HD;
#pragma unroll
        for (int j = 0; j < 8; ++j) {
            int idx = tid + j * 256;            // 0..2047
            int tsel = idx >> 10;
            int w = idx & 1023;
            int r = w >> 4, ck = w & 15;
            cpa16(sb + (tsel ? O_QL : O_QH) + r * APITCH + ck * 16,
                  (tsel ? qL : qH) + (size_t)r * HD + ck * 8);
        }
        cpa_commit();
    }

    const __nv_bfloat16* kH = Kh + (size_t)kvh * SEQ * HD;
    const __nv_bfloat16* kL = Kl + (size_t)kvh * SEQ * HD;
    const __nv_bfloat16* vH = Vh + (size_t)kvh * SEQ * HD;
    const __nv_bfloat16* vL = Vl + (size_t)kvh * SEQ * HD;

    float m_i[8], l_i[8], oacc[8][4];
#pragma unroll
    for (int r = 0; r < 8; ++r) { m_i[r] = -1e30f; l_i[r] = 0.f; }
#pragma unroll
    for (int t = 0; t < 8; ++t)
#pragma unroll
        for (int q = 0; q < 4; ++q) oacc[t][q] = 0.f;

    for (int kb = 0; kb <= qb; ++kb) {
        __syncthreads();   // previous PV done reading K/V/P before overwrite

        // load K,V hi/lo tiles of block kb
        const __nv_bfloat16* src[4] = {kH, kL, vH, vL};
#pragma unroll
        for (int j = 0; j < 16; ++j) {
            int idx = tid + j * 256;            // 0..4095
            int tsel = idx >> 10;
            int w = idx & 1023;
            int r = w >> 4, ck = w & 15;
            cpa16(sb + O_KH + tsel * ATILE + r * APITCH + ck * 16,
                  src[tsel] + ((size_t)(kb * 64 + r)) * HD + ck * 8);
        }
        cpa_commit();
        cpa_wait<0>();
        __syncthreads();

        // ---- QK: S = Qh*Kh + Qh*Kl + Ql*Kh ----
        float sf[4][4];
#pragma unroll
        for (int j = 0; j < 4; ++j)
#pragma unroll
            for (int q = 0; q < 4; ++q) sf[j][q] = 0.f;

        uint32_t aH = sb + O_QH + (wr * 16 + (lane & 15)) * APITCH + (lane >> 4) * 16;
        uint32_t aL = aH + ATILE;
        uint32_t bH = sb + O_KH + (wc * 32 + (lane & 7)) * APITCH + ((lane >> 3) & 1) * 16;
        uint32_t bL = bH + ATILE;
#pragma unroll
        for (int s = 0; s < 8; ++s) {
            uint32_t qh4[4], ql4[4];
            ldm_x4(qh4, aH + s * 32);
            ldm_x4(ql4, aL + s * 32);
#pragma unroll
            for (int j = 0; j < 4; ++j) {
                uint32_t kh2[2], kl2[2];
                ldm_x2(kh2, bH + j * 8 * APITCH + s * 32);
                ldm_x2(kl2, bL + j * 8 * APITCH + s * 32);
                mma16816(sf[j], qh4, kh2);
                mma16816(sf[j], qh4, kl2);
                mma16816(sf[j], ql4, kh2);
            }
        }

        // store S to smem with causal mask
        {
            int r0 = wr * 16 + (lane >> 2);
            int c0 = wc * 32 + (lane & 3) * 2;
            bool diag = (kb == qb);
#pragma unroll
            for (int j = 0; j < 4; ++j) {
                int c = c0 + j * 8;
                float v0 = sf[j][0], v1 = sf[j][1], v2 = sf[j][2], v3 = sf[j][3];
                if (diag) {
                    if (c > r0)         v0 = -1e30f;
                    if (c + 1 > r0)     v1 = -1e30f;
                    if (c > r0 + 8)     v2 = -1e30f;
                    if (c + 1 > r0 + 8) v3 = -1e30f;
                }
                SsF[r0 * SSP + c]           = v0;
                SsF[r0 * SSP + c + 1]       = v1;
                SsF[(r0 + 8) * SSP + c]     = v2;
                SsF[(r0 + 8) * SSP + c + 1] = v3;
            }
        }
        __syncthreads();

        // ---- softmax on owner rows (warp w owns rows w*8..w*8+7) ----
#pragma unroll
        for (int rr = 0; rr < 8; ++rr) {
            int r = warp * 8 + rr;
            float s0 = SsF[r * SSP + lane];
            float s1 = SsF[r * SSP + lane + 32];
            float mx = fmaxf(s0, s1);
#pragma unroll
            for (int o = 16; o > 0; o >>= 1)
                mx = fmaxf(mx, __shfl_xor_sync(0xFFFFFFFFu, mx, o));
            float m_new = fmaxf(m_i[rr], mx);
            float p0 = __expf(s0 - m_new);
            float p1 = __expf(s1 - m_new);
            SsF[r * SSP + lane]      = p0;
            SsF[r * SSP + lane + 32] = p1;
            float sum = p0 + p1;
#pragma unroll
            for (int o = 16; o > 0; o >>= 1)
                sum += __shfl_xor_sync(0xFFFFFFFFu, sum, o);
            float crr = __expf(m_i[rr] - m_new);
            l_i[rr] = l_i[rr] * crr + sum;
            m_i[rr] = m_new;
            if (lane == 0) corr[r] = crr;
        }
        __syncthreads();

        // ---- convert P -> bf16 hi/lo; scale O accumulators ----
#pragma unroll
        for (int j = 0; j < 8; ++j) {
            int i = tid + j * 256;              // 0..2047 float2 units
            int r = i >> 5;
            int c2 = (i & 31) * 2;
            float p0 = SsF[r * SSP + c2];
            float p1 = SsF[r * SSP + c2 + 1];
            __nv_bfloat16 h0 = __float2bfloat16(p0);
            __nv_bfloat16 h1 = __float2bfloat16(p1);
            *(__nv_bfloat162*)(smx + O_PH + r * PPITCH + c2 * 2) =
                __nv_bfloat162(h0, h1);
            *(__nv_bfloat162*)(smx + O_PL + r * PPITCH + c2 * 2) =
                __nv_bfloat162(__float2bfloat16(p0 - __bfloat162float(h0)),
                               __float2bfloat16(p1 - __bfloat162float(h1)));
        }
        {
            float cr0 = corr[wr * 16 + (lane >> 2)];
            float cr1 = corr[wr * 16 + (lane >> 2) + 8];
#pragma unroll
            for (int t = 0; t < 8; ++t) {
                oacc[t][0] *= cr0; oacc[t][1] *= cr0;
                oacc[t][2] *= cr1; oacc[t][3] *= cr1;
            }
        }
        __syncthreads();

        // ---- PV: O += Ph*Vh + Pl*Vh + Ph*Vl ----
        {
            uint32_t pH = sb + O_PH + (wr * 16 + (lane & 15)) * PPITCH + (lane >> 4) * 16;
            uint32_t pL = pH + (O_PL - O_PH);
            uint32_t vHb = sb + O_VH + (lane & 15) * APITCH + wc * 128;
            uint32_t vLb = vHb + ATILE;
#pragma unroll
            for (int s = 0; s < 4; ++s) {
                uint32_t ph4[4], pl4[4];
                ldm_x4(ph4, pH + s * 32);
                ldm_x4(pl4, pL + s * 32);
#pragma unroll
                for (int j = 0; j < 8; ++j) {
                    uint32_t vh2[2], vl2[2];
                    ldm_x2t(vh2, vHb + s * 16 * APITCH + j * 16);
                    ldm_x2t(vl2, vLb + s * 16 * APITCH + j * 16);
                    mma16816(oacc[j], ph4, vh2);
                    mma16816(oacc[j], pl4, vh2);
                    mma16816(oacc[j], ph4, vl2);
                }
            }
        }
    }

    // ---- epilogue ----
    __syncthreads();
    if (lane == 0) {
#pragma unroll
        for (int rr = 0; rr < 8; ++rr)
            linv[warp * 8 + rr] = 1.f / l_i[rr];
    }
    __syncthreads();

    {
        float li0 = linv[wr * 16 + (lane >> 2)];
        float li1 = linv[wr * 16 + (lane >> 2) + 8];
        int orow = qb * 64 + wr * 16 + (lane >> 2);
        int ocol = h * HD + wc * 64 + (lane & 3) * 2;
#pragma unroll
        for (int j = 0; j < 8; ++j) {
            int c = ocol + j * 8;
            float f0 = oacc[j][0] * li0, f1 = oacc[j][1] * li0;
            float f2 = oacc[j][2] * li1, f3 = oacc[j][3] * li1;
            __nv_bfloat16 h0 = __float2bfloat16(f0);
            __nv_bfloat16 h1 = __float2bfloat16(f1);
            __nv_bfloat16 h2 = __float2bfloat16(f2);
            __nv_bfloat16 h3 = __float2bfloat16(f3);
            *(__nv_bfloat162*)&outH[(size_t)orow * HID + c] = __nv_bfloat162(h0, h1);
            *(__nv_bfloat162*)&outL[(size_t)orow * HID + c] =
                __nv_bfloat162(__float2bfloat16(f0 - __bfloat162float(h0)),
                               __float2bfloat16(f1 - __bfloat162float(h1)));
            *(__nv_bfloat162*)&outH[(size_t)(orow + 8) * HID + c] = __nv_bfloat162(h2, h3);
            *(__nv_bfloat162*)&outL[(size_t)(orow + 8) * HID + c] =
                __nv_bfloat162(__float2bfloat16(f2 - __bfloat162float(h2)),
                               __float2bfloat16(f3 - __bfloat162float(h3)));
        }
    }
}

// ---------------------------------------------------------------------------
// kernel_launch
// ---------------------------------------------------------------------------
extern "C" void kernel_launch(void* const* d_in, const int* in_sizes, int n_in,
                              void* d_out, int out_size)
{
    const float* hs    = (const float*)d_in[0];
    const int*   pos   = (const int*)d_in[1];
    const float* w_qkv = (const float*)d_in[2];
    const float* w_o   = (const float*)d_in[3];
    float* out = (float*)d_out;

    float* qkv; cudaGetSymbolAddress((void**)&qkv, g_qkv);
    __nv_bfloat16 *Ah, *Al, *Bh, *Bl, *Qh, *Ql, *Kh, *Kl, *Vh, *Vl;
    cudaGetSymbolAddress((void**)&Ah, g_Ah);
    cudaGetSymbolAddress((void**)&Al, g_Al);
    cudaGetSymbolAddress((void**)&Bh, g_Bh);
    cudaGetSymbolAddress((void**)&Bl, g_Bl);
    cudaGetSymbolAddress((void**)&Qh, g_Qh);
    cudaGetSymbolAddress((void**)&Ql, g_Ql);
    cudaGetSymbolAddress((void**)&Kh, g_Kh);
    cudaGetSymbolAddress((void**)&Kl, g_Kl);
    cudaGetSymbolAddress((void**)&Vh, g_Vh);
    cudaGetSymbolAddress((void**)&Vl, g_Vl);

    cudaFuncSetAttribute(gemm_mma_kernel,
                         cudaFuncAttributeMaxDynamicSharedMemorySize, GEMM_SMEM);
    cudaFuncSetAttribute(flash_mma_kernel,
                         cudaFuncAttributeMaxDynamicSharedMemorySize, FL_SMEM);

    // 1) split hs ; transpose+split w_qkv
    split_kernel<<<(SEQ * HID / 4 + 255) / 256, 256>>>(hs, Ah, Al, SEQ * HID / 4);
    splitT_kernel<<<dim3(QKVN / 32, HID / 32), dim3(32, 8)>>>(w_qkv, Bh, Bl, HID, QKVN);

    // 2) QKV projection (tensor cores)
    gemm_mma_kernel<<<dim3(QKVN / 128, SEQ / 128), 256, GEMM_SMEM>>>(
        Ah, Al, Bh, Bl, qkv, HID, QKVN);

    // 3) RoPE + split into bf16 hi/lo Q/K/V [h][s][d]
    {
        int total = SEQ * (NH + 2 * NKV) * (HD / 2);
        rope_split_kernel<<<(total + 255) / 256, 256>>>(qkv, pos,
                                                        Qh, Ql, Kh, Kl, Vh, Vl);
    }

    // 4) Tensor-core flash attention -> bf16 hi/lo directly into Ah/Al
    flash_mma_kernel<<<dim3(SEQ / 64, NH), 256, FL_SMEM>>>(
        Qh, Ql, Kh, Kl, Vh, Vl, Ah, Al);

    // 5) transpose+split w_o
    splitT_kernel<<<dim3(HID / 32, HID / 32), dim3(32, 8)>>>(w_o, Bh, Bl, HID, HID);

    // 6) Output projection (tensor cores)
    gemm_mma_kernel<<<dim3(HID / 128, SEQ / 128), 256, GEMM_SMEM>>>(
        Ah, Al, Bh, Bl, out, HID, HID);
}

// round 8
// speedup vs baseline: 2.8773x; 1.0189x over previous
#include <cuda_runtime.h>
#include <cuda_bf16.h>
#include <stdint.h>
#include <math.h>

#define SEQ   2048
#define HID   4096
#define NH    32
#define NKV   8
#define HD    128
#define GRP   (NH / NKV)             // 4
#define QKVN  ((NH + 2 * NKV) * HD)  // 6144
#define ATTN_N (NH * HD)             // 4096

// ---------------------------------------------------------------------------
// Scratch (device globals; no allocations allowed)
// ---------------------------------------------------------------------------
__device__ float g_qkv[SEQ * QKVN];            // QKV output, fp32
__device__ __nv_bfloat16 g_Ah[SEQ * HID];      // GEMM A hi (hs / attn-out)
__device__ __nv_bfloat16 g_Al[SEQ * HID];      // GEMM A lo
__device__ __nv_bfloat16 g_Bh[QKVN * HID];     // B^T hi
__device__ __nv_bfloat16 g_Bl[QKVN * HID];     // B^T lo
__device__ __nv_bfloat16 g_Qh[NH * SEQ * HD];  // roped Q hi  [h][s][d]
__device__ __nv_bfloat16 g_Ql[NH * SEQ * HD];
__device__ __nv_bfloat16 g_Kh[NKV * SEQ * HD]; // roped K hi  [h][s][d]
__device__ __nv_bfloat16 g_Kl[NKV * SEQ * HD];
__device__ __nv_bfloat16 g_Vh[NKV * SEQ * HD]; // V hi        [h][s][d]
__device__ __nv_bfloat16 g_Vl[NKV * SEQ * HD];

// ---------------------------------------------------------------------------
// PTX helpers (portable: no 'a'-suffix features)
// ---------------------------------------------------------------------------
__device__ __forceinline__ uint32_t s2u(const void* p) {
    uint32_t a;
    asm("{ .reg .u64 t; cvta.to.shared.u64 t, %1; cvt.u32.u64 %0, t; }"
        : "=r"(a) : "l"(p));
    return a;
}

__device__ __forceinline__ void cpa16(uint32_t s, const void* g) {
    asm volatile("cp.async.cg.shared.global [%0], [%1], 16;" :: "r"(s), "l"(g));
}
__device__ __forceinline__ void cpa_commit() {
    asm volatile("cp.async.commit_group;" ::: "memory");
}
template <int N>
__device__ __forceinline__ void cpa_wait() {
    asm volatile("cp.async.wait_group %0;" :: "n"(N) : "memory");
}

__device__ __forceinline__ void ldm_x4(uint32_t* r, uint32_t addr) {
    asm volatile("ldmatrix.sync.aligned.m8n8.x4.shared.b16 {%0,%1,%2,%3}, [%4];"
                 : "=r"(r[0]), "=r"(r[1]), "=r"(r[2]), "=r"(r[3]) : "r"(addr));
}
__device__ __forceinline__ void ldm_x2(uint32_t* r, uint32_t addr) {
    asm volatile("ldmatrix.sync.aligned.m8n8.x2.shared.b16 {%0,%1}, [%2];"
                 : "=r"(r[0]), "=r"(r[1]) : "r"(addr));
}
__device__ __forceinline__ void ldm_x2t(uint32_t* r, uint32_t addr) {
    asm volatile("ldmatrix.sync.aligned.m8n8.x2.trans.shared.b16 {%0,%1}, [%2];"
                 : "=r"(r[0]), "=r"(r[1]) : "r"(addr));
}

__device__ __forceinline__ void mma16816(float* c, const uint32_t* a, const uint32_t* b) {
    asm volatile(
        "mma.sync.aligned.m16n8k16.row.col.f32.bf16.bf16.f32 "
        "{%0,%1,%2,%3}, {%4,%5,%6,%7}, {%8,%9}, {%0,%1,%2,%3};"
        : "+f"(c[0]), "+f"(c[1]), "+f"(c[2]), "+f"(c[3])
        : "r"(a[0]), "r"(a[1]), "r"(a[2]), "r"(a[3]), "r"(b[0]), "r"(b[1]));
}

// ---------------------------------------------------------------------------
// Split fp32 -> bf16 hi + lo (elementwise, float4)
// ---------------------------------------------------------------------------
__global__ void split_kernel(const float* __restrict__ in,
                             __nv_bfloat16* __restrict__ hi,
                             __nv_bfloat16* __restrict__ lo, int n4)
{
    int i = blockIdx.x * blockDim.x + threadIdx.x;
    if (i >= n4) return;
    float4 v = ((const float4*)in)[i];
    __nv_bfloat16 h0 = __float2bfloat16(v.x);
    __nv_bfloat16 h1 = __float2bfloat16(v.y);
    __nv_bfloat16 h2 = __float2bfloat16(v.z);
    __nv_bfloat16 h3 = __float2bfloat16(v.w);
    __nv_bfloat16 l0 = __float2bfloat16(v.x - __bfloat162float(h0));
    __nv_bfloat16 l1 = __float2bfloat16(v.y - __bfloat162float(h1));
    __nv_bfloat16 l2 = __float2bfloat16(v.z - __bfloat162float(h2));
    __nv_bfloat16 l3 = __float2bfloat16(v.w - __bfloat162float(h3));
    __nv_bfloat162* hp = (__nv_bfloat162*)hi;
    __nv_bfloat162* lp = (__nv_bfloat162*)lo;
    hp[2 * i]     = __nv_bfloat162(h0, h1);
    hp[2 * i + 1] = __nv_bfloat162(h2, h3);
    lp[2 * i]     = __nv_bfloat162(l0, l1);
    lp[2 * i + 1] = __nv_bfloat162(l2, l3);
}

// ---------------------------------------------------------------------------
// Transpose + split: in fp32 [K,N] row-major -> hi/lo bf16 [N,K]
// ---------------------------------------------------------------------------
__global__ void splitT_kernel(const float* __restrict__ in,
                              __nv_bfloat16* __restrict__ hi,
                              __nv_bfloat16* __restrict__ lo, int K, int N)
{
    __shared__ float t[32][33];
    int n0 = blockIdx.x * 32, k0 = blockIdx.y * 32;
    int tx = threadIdx.x, ty = threadIdx.y;   // 32 x 8
#pragma unroll
    for (int j = 0; j < 4; j++)
        t[ty + 8 * j][tx] = in[(size_t)(k0 + ty + 8 * j) * N + n0 + tx];
    __syncthreads();
#pragma unroll
    for (int j = 0; j < 4; j++) {
        float a = t[tx][ty + 8 * j];
        size_t o = (size_t)(n0 + ty + 8 * j) * K + k0 + tx;
        __nv_bfloat16 h = __float2bfloat16(a);
        hi[o] = h;
        lo[o] = __float2bfloat16(a - __bfloat162float(h));
    }
}

// ---------------------------------------------------------------------------
// mma.sync GEMM, bf16x3 fp32 emulation. CTA 128x128, KC=64.
// 3-stage cp.async pipeline, single __syncthreads per chunk.
// ---------------------------------------------------------------------------
#define KC      64
#define PITCH_B 144
#define TILE_SB (128 * PITCH_B)
#define STAGE_B (4 * TILE_SB)            // 73728
#define GEMM_SMEM (3 * STAGE_B)          // 221184

__global__ __launch_bounds__(256, 1)
void gemm_mma_kernel(const __nv_bfloat16* __restrict__ Ah,
                     const __nv_bfloat16* __restrict__ Al,
                     const __nv_bfloat16* __restrict__ Bh,
                     const __nv_bfloat16* __restrict__ Bl,
                     float* __restrict__ C, int K, int Nc)
{
    extern __shared__ char smc[];
    const uint32_t sbase = s2u(smc);

    const int tid  = threadIdx.x;
    const int lane = tid & 31;
    const int warp = tid >> 5;
    const int wm = warp >> 2;
    const int wn = warp & 3;
    const int bm = blockIdx.y, bn = blockIdx.x;
    const int nchunk = K / KC;

    const __nv_bfloat16* gsrc[4] = {Ah, Al, Bh, Bl};
    const int row0[4] = {bm * 128, bm * 128, bn * 128, bn * 128};

    auto load_stage = [&](int c, int s) {
        uint32_t stg = sbase + s * STAGE_B;
        int kt = c * KC;
#pragma unroll
        for (int j = 0; j < 16; ++j) {
            int idx  = tid + j * 256;
            int tsel = idx >> 10;
            int w    = idx & 1023;
            int r    = w >> 3;
            int ck   = w & 7;
            cpa16(stg + tsel * TILE_SB + r * PITCH_B + ck * 16,
                  gsrc[tsel] + (size_t)(row0[tsel] + r) * K + kt + ck * 8);
        }
    };

    float acc[4][4][4];
#pragma unroll
    for (int i = 0; i < 4; i++)
#pragma unroll
        for (int j = 0; j < 4; j++)
#pragma unroll
            for (int q = 0; q < 4; q++) acc[i][j][q] = 0.f;

    load_stage(0, 0); cpa_commit();
    load_stage(1, 1); cpa_commit();

    int scur = 0;        // stage of chunk c
    int sload = 2;       // stage for chunk c+2
    for (int c = 0; c < nchunk; ++c) {
        cpa_wait<1>();          // chunk c's group complete (c+1 may be pending)
        __syncthreads();

        if (c + 2 < nchunk) {
            load_stage(c + 2, sload);
            cpa_commit();
        }

        uint32_t stg = sbase + scur * STAGE_B;
        uint32_t aBaseH = stg + (wm * 64 + (lane & 15)) * PITCH_B + (lane >> 4) * 16;
        uint32_t aBaseL = aBaseH + TILE_SB;
        uint32_t bBaseH = stg + 2 * TILE_SB +
                          (wn * 32 + (lane & 7)) * PITCH_B + ((lane >> 3) & 1) * 16;
        uint32_t bBaseL = bBaseH + TILE_SB;

#pragma unroll
        for (int s = 0; s < 4; ++s) {
            uint32_t ah[4][4], al[4][4], bh[4][2], bl[4][2];
#pragma unroll
            for (int i = 0; i < 4; ++i) {
                ldm_x4(ah[i], aBaseH + i * 16 * PITCH_B + s * 32);
                ldm_x4(al[i], aBaseL + i * 16 * PITCH_B + s * 32);
            }
#pragma unroll
            for (int j = 0; j < 4; ++j) {
                ldm_x2(bh[j], bBaseH + j * 8 * PITCH_B + s * 32);
                ldm_x2(bl[j], bBaseL + j * 8 * PITCH_B + s * 32);
            }
#pragma unroll
            for (int i = 0; i < 4; ++i)
#pragma unroll
                for (int j = 0; j < 4; ++j) {
                    mma16816(acc[i][j], ah[i], bh[j]);
                    mma16816(acc[i][j], ah[i], bl[j]);
                    mma16816(acc[i][j], al[i], bh[j]);
                }
        }

        scur = (scur == 2) ? 0 : scur + 1;
        sload = (sload == 2) ? 0 : sload + 1;
    }

    const int rbase = bm * 128 + wm * 64 + (lane >> 2);
    const int cbase = bn * 128 + wn * 32 + (lane & 3) * 2;
#pragma unroll
    for (int i = 0; i < 4; ++i) {
#pragma unroll
        for (int j = 0; j < 4; ++j) {
            int r = rbase + i * 16;
            int col = cbase + j * 8;
            *(float2*)&C[(size_t)r * Nc + col] =
                make_float2(acc[i][j][0], acc[i][j][1]);
            *(float2*)&C[(size_t)(r + 8) * Nc + col] =
                make_float2(acc[i][j][2], acc[i][j][3]);
        }
    }
}

// ---------------------------------------------------------------------------
// RoPE + hi/lo split: fp32 qkv -> bf16 hi/lo Q (scaled), K, V in [h][s][d].
// ---------------------------------------------------------------------------
__global__ void rope_split_kernel(const float* __restrict__ qkv,
                                  const int* __restrict__ positions,
                                  __nv_bfloat16* __restrict__ Qh, __nv_bfloat16* __restrict__ Ql,
                                  __nv_bfloat16* __restrict__ Kh, __nv_bfloat16* __restrict__ Kl,
                                  __nv_bfloat16* __restrict__ Vh, __nv_bfloat16* __restrict__ Vl)
{
    int idx = blockIdx.x * blockDim.x + threadIdx.x;
    const int NHTOT = NH + 2 * NKV;  // 48
    const int TOTAL = SEQ * NHTOT * (HD / 2);
    if (idx >= TOTAL) return;

    int d = idx & 63;
    int h = (idx >> 6) % NHTOT;
    int s = idx / (NHTOT * 64);

    const float* base = qkv + (size_t)s * QKVN + h * HD;
    float x1 = base[d];
    float x2 = base[d + 64];
    float y1 = x1, y2 = x2;

    if (h < NH + NKV) {
        float pos = (float)positions[s];
        float inv = powf(10000.0f, -(2.0f * (float)d) / (float)HD);
        float ang = pos * inv;
        float c, sn;
        sincosf(ang, &sn, &c);
        y1 = x1 * c - x2 * sn;
        y2 = x2 * c + x1 * sn;
    }

    __nv_bfloat16 *dh, *dl;
    size_t off;
    if (h < NH) {
        const float scale = 0.088388347648318447f;
        y1 *= scale; y2 *= scale;
        dh = Qh; dl = Ql;
        off = ((size_t)h * SEQ + s) * HD + d;
    } else if (h < NH + NKV) {
        dh = Kh; dl = Kl;
        off = ((size_t)(h - NH) * SEQ + s) * HD + d;
    } else {
        dh = Vh; dl = Vl;
        off = ((size_t)(h - NH - NKV) * SEQ + s) * HD + d;
    }
    __nv_bfloat16 h1 = __float2bfloat16(y1);
    __nv_bfloat16 h2 = __float2bfloat16(y2);
    dh[off]      = h1;
    dh[off + 64] = h2;
    dl[off]      = __float2bfloat16(y1 - __bfloat162float(h1));
    dl[off + 64] = __float2bfloat16(y2 - __bfloat162float(h2));
}

// ---------------------------------------------------------------------------
// Tensor-core flash attention (bf16x3), causal, GQA. Br=Bc=64, 256 threads.
// Double-buffered K/V via cp.async; output written as bf16 hi/lo.
// ---------------------------------------------------------------------------
#define APITCH 272
#define PPITCH 144
#define SSP    68
#define ATILE  (64 * APITCH)            // 17408
#define KVSTG  (4 * ATILE)              // 69632 (KH,KL,VH,VL)
#define O_QH   0
#define O_QL   (O_QH + ATILE)
#define O_KV0  (O_QL + ATILE)           // 34816
#define O_SS   (O_KV0 + 2 * KVSTG)      // 174080
#define O_PH   (O_SS + 64 * SSP * 4)    // 191488
#define O_PL   (O_PH + 64 * PPITCH)     // 200704
#define O_CORR (O_PL + 64 * PPITCH)     // 209920
#define O_LINV (O_CORR + 256)
#define FL_SMEM (O_LINV + 256)          // 210432

__global__ __launch_bounds__(256, 1)
void flash_mma_kernel(const __nv_bfloat16* __restrict__ Qh, const __nv_bfloat16* __restrict__ Ql,
                      const __nv_bfloat16* __restrict__ Kh, const __nv_bfloat16* __restrict__ Kl,
                      const __nv_bfloat16* __restrict__ Vh, const __nv_bfloat16* __restrict__ Vl,
                      __nv_bfloat16* __restrict__ outH, __nv_bfloat16* __restrict__ outL)
{
    extern __shared__ char smx[];
    const uint32_t sb = s2u(smx);
    float* SsF  = (float*)(smx + O_SS);
    float* corr = (float*)(smx + O_CORR);
    float* linv = (float*)(smx + O_LINV);

    const int qb = (int)gridDim.x - 1 - (int)blockIdx.x;  // longest first
    const int h  = blockIdx.y;
    const int kvh = h / GRP;

    const int tid  = threadIdx.x;
    const int warp = tid >> 5;
    const int lane = tid & 31;
    const int wr = warp & 3;
    const int wc = warp >> 2;

    const __nv_bfloat16* kH = Kh + (size_t)kvh * SEQ * HD;
    const __nv_bfloat16* kL = Kl + (size_t)kvh * SEQ * HD;
    const __nv_bfloat16* vH = Vh + (size_t)kvh * SEQ * HD;
    const __nv_bfloat16* vL = Vl + (size_t)kvh * SEQ * HD;
    const __nv_bfloat16* kvsrc[4] = {kH, kL, vH, vL};

    auto load_kv = [&](int kb, int buf) {
#pragma unroll
        for (int j = 0; j < 16; ++j) {
            int idx = tid + j * 256;
            int tsel = idx >> 10;
            int w = idx & 1023;
            int r = w >> 4, ck = w & 15;
            cpa16(sb + O_KV0 + buf * KVSTG + tsel * ATILE + r * APITCH + ck * 16,
                  kvsrc[tsel] + ((size_t)(kb * 64 + r)) * HD + ck * 8);
        }
    };

    // --- prologue: Q tiles + KV block 0 ---
    {
        const __nv_bfloat16* qH = Qh + ((size_t)h * SEQ + qb * 64) * HD;
        const __nv_bfloat16* qL = Ql + ((size_t)h * SEQ + qb * 64) * HD;
#pragma unroll
        for (int j = 0; j < 8; ++j) {
            int idx = tid + j * 256;
            int tsel = idx >> 10;
            int w = idx & 1023;
            int r = w >> 4, ck = w & 15;
            cpa16(sb + (tsel ? O_QL : O_QH) + r * APITCH + ck * 16,
                  (tsel ? qL : qH) + (size_t)r * HD + ck * 8);
        }
        cpa_commit();
    }
    load_kv(0, 0);
    cpa_commit();

    float m_i[8], l_i[8], oacc[8][4];
#pragma unroll
    for (int r = 0; r < 8; ++r) { m_i[r] = -1e30f; l_i[r] = 0.f; }
#pragma unroll
    for (int t = 0; t < 8; ++t)
#pragma unroll
        for (int q = 0; q < 4; ++q) oacc[t][q] = 0.f;

    for (int kb = 0; kb <= qb; ++kb) {
        const int buf = kb & 1;
        cpa_wait<0>();      // KV kb (and Q on first iter) resident
        __syncthreads();    // all smem writes visible; prev iter reads done

        if (kb + 1 <= qb) {
            load_kv(kb + 1, buf ^ 1);
            cpa_commit();
        }

        const uint32_t kvb = sb + O_KV0 + buf * KVSTG;

        // ---- QK: S = Qh*Kh + Qh*Kl + Ql*Kh ----
        float sf[4][4];
#pragma unroll
        for (int j = 0; j < 4; ++j)
#pragma unroll
            for (int q = 0; q < 4; ++q) sf[j][q] = 0.f;

        uint32_t aH = sb + O_QH + (wr * 16 + (lane & 15)) * APITCH + (lane >> 4) * 16;
        uint32_t aL = aH + ATILE;
        uint32_t bH = kvb + (wc * 32 + (lane & 7)) * APITCH + ((lane >> 3) & 1) * 16;
        uint32_t bL = bH + ATILE;
#pragma unroll
        for (int s = 0; s < 8; ++s) {
            uint32_t qh4[4], ql4[4];
            ldm_x4(qh4, aH + s * 32);
            ldm_x4(ql4, aL + s * 32);
#pragma unroll
            for (int j = 0; j < 4; ++j) {
                uint32_t kh2[2], kl2[2];
                ldm_x2(kh2, bH + j * 8 * APITCH + s * 32);
                ldm_x2(kl2, bL + j * 8 * APITCH + s * 32);
                mma16816(sf[j], qh4, kh2);
                mma16816(sf[j], qh4, kl2);
                mma16816(sf[j], ql4, kh2);
            }
        }

        // store S to smem with causal mask
        {
            int r0 = wr * 16 + (lane >> 2);
            int c0 = wc * 32 + (lane & 3) * 2;
            bool diag = (kb == qb);
#pragma unroll
            for (int j = 0; j < 4; ++j) {
                int c = c0 + j * 8;
                float v0 = sf[j][0], v1 = sf[j][1], v2 = sf[j][2], v3 = sf[j][3];
                if (diag) {
                    if (c > r0)         v0 = -1e30f;
                    if (c + 1 > r0)     v1 = -1e30f;
                    if (c > r0 + 8)     v2 = -1e30f;
                    if (c + 1 > r0 + 8) v3 = -1e30f;
                }
                SsF[r0 * SSP + c]           = v0;
                SsF[r0 * SSP + c + 1]       = v1;
                SsF[(r0 + 8) * SSP + c]     = v2;
                SsF[(r0 + 8) * SSP + c + 1] = v3;
            }
        }
        __syncthreads();

        // ---- softmax on owner rows ----
#pragma unroll
        for (int rr = 0; rr < 8; ++rr) {
            int r = warp * 8 + rr;
            float s0 = SsF[r * SSP + lane];
            float s1 = SsF[r * SSP + lane + 32];
            float mx = fmaxf(s0, s1);
#pragma unroll
            for (int o = 16; o > 0; o >>= 1)
                mx = fmaxf(mx, __shfl_xor_sync(0xFFFFFFFFu, mx, o));
            float m_new = fmaxf(m_i[rr], mx);
            float p0 = __expf(s0 - m_new);
            float p1 = __expf(s1 - m_new);
            SsF[r * SSP + lane]      = p0;
            SsF[r * SSP + lane + 32] = p1;
            float sum = p0 + p1;
#pragma unroll
            for (int o = 16; o > 0; o >>= 1)
                sum += __shfl_xor_sync(0xFFFFFFFFu, sum, o);
            float crr = __expf(m_i[rr] - m_new);
            l_i[rr] = l_i[rr] * crr + sum;
            m_i[rr] = m_new;
            if (lane == 0) corr[r] = crr;
        }
        __syncthreads();

        // ---- convert P -> bf16 hi/lo; scale O accumulators ----
#pragma unroll
        for (int j = 0; j < 8; ++j) {
            int i = tid + j * 256;
            int r = i >> 5;
            int c2 = (i & 31) * 2;
            float p0 = SsF[r * SSP + c2];
            float p1 = SsF[r * SSP + c2 + 1];
            __nv_bfloat16 h0 = __float2bfloat16(p0);
            __nv_bfloat16 h1 = __float2bfloat16(p1);
            *(__nv_bfloat162*)(smx + O_PH + r * PPITCH + c2 * 2) =
                __nv_bfloat162(h0, h1);
            *(__nv_bfloat162*)(smx + O_PL + r * PPITCH + c2 * 2) =
                __nv_bfloat162(__float2bfloat16(p0 - __bfloat162float(h0)),
                               __float2bfloat16(p1 - __bfloat162float(h1)));
        }
        {
            float cr0 = corr[wr * 16 + (lane >> 2)];
            float cr1 = corr[wr * 16 + (lane >> 2) + 8];
#pragma unroll
            for (int t = 0; t < 8; ++t) {
                oacc[t][0] *= cr0; oacc[t][1] *= cr0;
                oacc[t][2] *= cr1; oacc[t][3] *= cr1;
            }
        }
        __syncthreads();

        // ---- PV: O += Ph*Vh + Pl*Vh + Ph*Vl ----
        {
            uint32_t pH = sb + O_PH + (wr * 16 + (lane & 15)) * PPITCH + (lane >> 4) * 16;
            uint32_t pL = pH + (O_PL - O_PH);
            uint32_t vHb = kvb + 2 * ATILE + (lane & 15) * APITCH + wc * 128;
            uint32_t vLb = vHb + ATILE;
#pragma unroll
            for (int s = 0; s < 4; ++s) {
                uint32_t ph4[4], pl4[4];
                ldm_x4(ph4, pH + s * 32);
                ldm_x4(pl4, pL + s * 32);
#pragma unroll
                for (int j = 0; j < 8; ++j) {
                    uint32_t vh2[2], vl2[2];
                    ldm_x2t(vh2, vHb + s * 16 * APITCH + j * 16);
                    ldm_x2t(vl2, vLb + s * 16 * APITCH + j * 16);
                    mma16816(oacc[j], ph4, vh2);
                    mma16816(oacc[j], pl4, vh2);
                    mma16816(oacc[j], ph4, vl2);
                }
            }
        }
    }

    // ---- epilogue ----
    __syncthreads();
    if (lane == 0) {
#pragma unroll
        for (int rr = 0; rr < 8; ++rr)
            linv[warp * 8 + rr] = 1.f / l_i[rr];
    }
    __syncthreads();

    {
        float li0 = linv[wr * 16 + (lane >> 2)];
        float li1 = linv[wr * 16 + (lane >> 2) + 8];
        int orow = qb * 64 + wr * 16 + (lane >> 2);
        int ocol = h * HD + wc * 64 + (lane & 3) * 2;
#pragma unroll
        for (int j = 0; j < 8; ++j) {
            int c = ocol + j * 8;
            float f0 = oacc[j][0] * li0, f1 = oacc[j][1] * li0;
            float f2 = oacc[j][2] * li1, f3 = oacc[j][3] * li1;
            __nv_bfloat16 h0 = __float2bfloat16(f0);
            __nv_bfloat16 h1 = __float2bfloat16(f1);
            __nv_bfloat16 h2 = __float2bfloat16(f2);
            __nv_bfloat16 h3 = __float2bfloat16(f3);
            *(__nv_bfloat162*)&outH[(size_t)orow * HID + c] = __nv_bfloat162(h0, h1);
            *(__nv_bfloat162*)&outL[(size_t)orow * HID + c] =
                __nv_bfloat162(__float2bfloat16(f0 - __bfloat162float(h0)),
                               __float2bfloat16(f1 - __bfloat162float(h1)));
            *(__nv_bfloat162*)&outH[(size_t)(orow + 8) * HID + c] = __nv_bfloat162(h2, h3);
            *(__nv_bfloat162*)&outL[(size_t)(orow + 8) * HID + c] =
                __nv_bfloat162(__float2bfloat16(f2 - __bfloat162float(h2)),
                               __float2bfloat16(f3 - __bfloat162float(h3)));
        }
    }
}

// ---------------------------------------------------------------------------
// kernel_launch
// ---------------------------------------------------------------------------
extern "C" void kernel_launch(void* const* d_in, const int* in_sizes, int n_in,
                              void* d_out, int out_size)
{
    const float* hs    = (const float*)d_in[0];
    const int*   pos   = (const int*)d_in[1];
    const float* w_qkv = (const float*)d_in[2];
    const float* w_o   = (const float*)d_in[3];
    float* out = (float*)d_out;

    float* qkv; cudaGetSymbolAddress((void**)&qkv, g_qkv);
    __nv_bfloat16 *Ah, *Al, *Bh, *Bl, *Qh, *Ql, *Kh, *Kl, *Vh, *Vl;
    cudaGetSymbolAddress((void**)&Ah, g_Ah);
    cudaGetSymbolAddress((void**)&Al, g_Al);
    cudaGetSymbolAddress((void**)&Bh, g_Bh);
    cudaGetSymbolAddress((void**)&Bl, g_Bl);
    cudaGetSymbolAddress((void**)&Qh, g_Qh);
    cudaGetSymbolAddress((void**)&Ql, g_Ql);
    cudaGetSymbolAddress((void**)&Kh, g_Kh);
    cudaGetSymbolAddress((void**)&Kl, g_Kl);
    cudaGetSymbolAddress((void**)&Vh, g_Vh);
    cudaGetSymbolAddress((void**)&Vl, g_Vl);

    cudaFuncSetAttribute(gemm_mma_kernel,
                         cudaFuncAttributeMaxDynamicSharedMemorySize, GEMM_SMEM);
    cudaFuncSetAttribute(flash_mma_kernel,
                         cudaFuncAttributeMaxDynamicSharedMemorySize, FL_SMEM);

    // 1) split hs ; transpose+split w_qkv
    split_kernel<<<(SEQ * HID / 4 + 255) / 256, 256>>>(hs, Ah, Al, SEQ * HID / 4);
    splitT_kernel<<<dim3(QKVN / 32, HID / 32), dim3(32, 8)>>>(w_qkv, Bh, Bl, HID, QKVN);

    // 2) QKV projection (tensor cores)
    gemm_mma_kernel<<<dim3(QKVN / 128, SEQ / 128), 256, GEMM_SMEM>>>(
        Ah, Al, Bh, Bl, qkv, HID, QKVN);

    // 3) RoPE + split into bf16 hi/lo Q/K/V [h][s][d]
    {
        int total = SEQ * (NH + 2 * NKV) * (HD / 2);
        rope_split_kernel<<<(total + 255) / 256, 256>>>(qkv, pos,
                                                        Qh, Ql, Kh, Kl, Vh, Vl);
    }

    // 4) Tensor-core flash attention -> bf16 hi/lo directly into Ah/Al
    flash_mma_kernel<<<dim3(SEQ / 64, NH), 256, FL_SMEM>>>(
        Qh, Ql, Kh, Kl, Vh, Vl, Ah, Al);

    // 5) transpose+split w_o
    splitT_kernel<<<dim3(HID / 32, HID / 32), dim3(32, 8)>>>(w_o, Bh, Bl, HID, HID);

    // 6) Output projection (tensor cores)
    gemm_mma_kernel<<<dim3(HID / 128, SEQ / 128), 256, GEMM_SMEM>>>(
        Ah, Al, Bh, Bl, out, HID, HID);
}

// round 9
// speedup vs baseline: 3.8674x; 1.3441x over previous
#include <cuda_runtime.h>
#include <cuda_fp16.h>
#include <stdint.h>
#include <math.h>

#define SEQ   2048
#define HID   4096
#define NH    32
#define NKV   8
#define HD    128
#define GRP   (NH / NKV)             // 4
#define QKVN  ((NH + 2 * NKV) * HD)  // 6144

// ---------------------------------------------------------------------------
// Scratch (device globals; no allocations allowed)
// ---------------------------------------------------------------------------
__device__ float g_qkv[SEQ * QKVN];        // QKV output, fp32
__device__ __half g_Ah[SEQ * HID];         // GEMM A hi (hs / attn-out)
__device__ __half g_Al[SEQ * HID];         // GEMM A lo
__device__ __half g_Bh[QKVN * HID];        // B^T hi (fp16 weights)
__device__ __half g_Qh[NH * SEQ * HD];     // roped Q hi  [h][s][d]
__device__ __half g_Ql[NH * SEQ * HD];     // roped Q lo
__device__ __half g_Kh[NKV * SEQ * HD];    // roped K hi  [h][s][d]
__device__ __half g_Vh[NKV * SEQ * HD];    // V hi        [h][s][d]

// ---------------------------------------------------------------------------
// PTX helpers (portable: no 'a'-suffix features)
// ---------------------------------------------------------------------------
__device__ __forceinline__ uint32_t s2u(const void* p) {
    uint32_t a;
    asm("{ .reg .u64 t; cvta.to.shared.u64 t, %1; cvt.u32.u64 %0, t; }"
        : "=r"(a) : "l"(p));
    return a;
}

__device__ __forceinline__ void cpa16(uint32_t s, const void* g) {
    asm volatile("cp.async.cg.shared.global [%0], [%1], 16;" :: "r"(s), "l"(g));
}
__device__ __forceinline__ void cpa_commit() {
    asm volatile("cp.async.commit_group;" ::: "memory");
}
template <int N>
__device__ __forceinline__ void cpa_wait() {
    asm volatile("cp.async.wait_group %0;" :: "n"(N) : "memory");
}

__device__ __forceinline__ void ldm_x4(uint32_t* r, uint32_t addr) {
    asm volatile("ldmatrix.sync.aligned.m8n8.x4.shared.b16 {%0,%1,%2,%3}, [%4];"
                 : "=r"(r[0]), "=r"(r[1]), "=r"(r[2]), "=r"(r[3]) : "r"(addr));
}
__device__ __forceinline__ void ldm_x2(uint32_t* r, uint32_t addr) {
    asm volatile("ldmatrix.sync.aligned.m8n8.x2.shared.b16 {%0,%1}, [%2];"
                 : "=r"(r[0]), "=r"(r[1]) : "r"(addr));
}
__device__ __forceinline__ void ldm_x2t(uint32_t* r, uint32_t addr) {
    asm volatile("ldmatrix.sync.aligned.m8n8.x2.trans.shared.b16 {%0,%1}, [%2];"
                 : "=r"(r[0]), "=r"(r[1]) : "r"(addr));
}

// fp16 inputs, fp32 accumulate
__device__ __forceinline__ void mma16816(float* c, const uint32_t* a, const uint32_t* b) {
    asm volatile(
        "mma.sync.aligned.m16n8k16.row.col.f32.f16.f16.f32 "
        "{%0,%1,%2,%3}, {%4,%5,%6,%7}, {%8,%9}, {%0,%1,%2,%3};"
        : "+f"(c[0]), "+f"(c[1]), "+f"(c[2]), "+f"(c[3])
        : "r"(a[0]), "r"(a[1]), "r"(a[2]), "r"(a[3]), "r"(b[0]), "r"(b[1]));
}

// ---------------------------------------------------------------------------
// Split fp32 -> fp16 hi + lo (elementwise, float4)
// ---------------------------------------------------------------------------
__global__ void split_kernel(const float* __restrict__ in,
                             __half* __restrict__ hi,
                             __half* __restrict__ lo, int n4)
{
    int i = blockIdx.x * blockDim.x + threadIdx.x;
    if (i >= n4) return;
    float4 v = ((const float4*)in)[i];
    __half h0 = __float2half_rn(v.x);
    __half h1 = __float2half_rn(v.y);
    __half h2 = __float2half_rn(v.z);
    __half h3 = __float2half_rn(v.w);
    __half l0 = __float2half_rn(v.x - __half2float(h0));
    __half l1 = __float2half_rn(v.y - __half2float(h1));
    __half l2 = __float2half_rn(v.z - __half2float(h2));
    __half l3 = __float2half_rn(v.w - __half2float(h3));
    __half2* hp = (__half2*)hi;
    __half2* lp = (__half2*)lo;
    hp[2 * i]     = __halves2half2(h0, h1);
    hp[2 * i + 1] = __halves2half2(h2, h3);
    lp[2 * i]     = __halves2half2(l0, l1);
    lp[2 * i + 1] = __halves2half2(l2, l3);
}

// ---------------------------------------------------------------------------
// Transpose + fp16 round (hi only): fp32 [K,N] row-major -> fp16 [N,K]
// ---------------------------------------------------------------------------
__global__ void transT_kernel(const float* __restrict__ in,
                              __half* __restrict__ hi, int K, int N)
{
    __shared__ float t[32][33];
    int n0 = blockIdx.x * 32, k0 = blockIdx.y * 32;
    int tx = threadIdx.x, ty = threadIdx.y;   // 32 x 8
#pragma unroll
    for (int j = 0; j < 4; j++)
        t[ty + 8 * j][tx] = in[(size_t)(k0 + ty + 8 * j) * N + n0 + tx];
    __syncthreads();
#pragma unroll
    for (int j = 0; j < 4; j++) {
        float a = t[tx][ty + 8 * j];
        hi[(size_t)(n0 + ty + 8 * j) * K + k0 + tx] = __float2half_rn(a);
    }
}

// ---------------------------------------------------------------------------
// mma.sync GEMM, fp16 2-term emulation: C = Ah*Bh + Al*Bh.
// CTA 128x128, KC=64, 3-stage cp.async pipeline, 3 tiles/stage (Ah,Al,Bh).
// ---------------------------------------------------------------------------
#define KC      64
#define PITCH_B 144
#define TILE_SB (128 * PITCH_B)
#define STAGE_B (3 * TILE_SB)            // 55296
#define GEMM_SMEM (3 * STAGE_B)          // 165888

__global__ __launch_bounds__(256, 1)
void gemm_mma_kernel(const __half* __restrict__ Ah,
                     const __half* __restrict__ Al,
                     const __half* __restrict__ Bh,
                     float* __restrict__ C, int K, int Nc)
{
    extern __shared__ char smc[];
    const uint32_t sbase = s2u(smc);

    const int tid  = threadIdx.x;
    const int lane = tid & 31;
    const int warp = tid >> 5;
    const int wm = warp >> 2;
    const int wn = warp & 3;
    const int bm = blockIdx.y, bn = blockIdx.x;
    const int nchunk = K / KC;

    const __half* gsrc[3] = {Ah, Al, Bh};
    const int row0[3] = {bm * 128, bm * 128, bn * 128};

    auto load_stage = [&](int c, int s) {
        uint32_t stg = sbase + s * STAGE_B;
        int kt = c * KC;
#pragma unroll
        for (int j = 0; j < 12; ++j) {           // 3 tiles * 1024 chunks
            int idx  = tid + j * 256;
            int tsel = idx >> 10;
            int w    = idx & 1023;
            int r    = w >> 3;
            int ck   = w & 7;
            cpa16(stg + tsel * TILE_SB + r * PITCH_B + ck * 16,
                  gsrc[tsel] + (size_t)(row0[tsel] + r) * K + kt + ck * 8);
        }
    };

    float acc[4][4][4];
#pragma unroll
    for (int i = 0; i < 4; i++)
#pragma unroll
        for (int j = 0; j < 4; j++)
#pragma unroll
            for (int q = 0; q < 4; q++) acc[i][j][q] = 0.f;

    load_stage(0, 0); cpa_commit();
    load_stage(1, 1); cpa_commit();

    int scur = 0, sload = 2;
    for (int c = 0; c < nchunk; ++c) {
        cpa_wait<1>();
        __syncthreads();

        if (c + 2 < nchunk) {
            load_stage(c + 2, sload);
            cpa_commit();
        }

        uint32_t stg = sbase + scur * STAGE_B;
        uint32_t aBaseH = stg + (wm * 64 + (lane & 15)) * PITCH_B + (lane >> 4) * 16;
        uint32_t aBaseL = aBaseH + TILE_SB;
        uint32_t bBaseH = stg + 2 * TILE_SB +
                          (wn * 32 + (lane & 7)) * PITCH_B + ((lane >> 3) & 1) * 16;

#pragma unroll
        for (int s = 0; s < 4; ++s) {
            uint32_t ah[4][4], al[4][4], bh[4][2];
#pragma unroll
            for (int i = 0; i < 4; ++i) {
                ldm_x4(ah[i], aBaseH + i * 16 * PITCH_B + s * 32);
                ldm_x4(al[i], aBaseL + i * 16 * PITCH_B + s * 32);
            }
#pragma unroll
            for (int j = 0; j < 4; ++j)
                ldm_x2(bh[j], bBaseH + j * 8 * PITCH_B + s * 32);
#pragma unroll
            for (int i = 0; i < 4; ++i)
#pragma unroll
                for (int j = 0; j < 4; ++j) {
                    mma16816(acc[i][j], ah[i], bh[j]);
                    mma16816(acc[i][j], al[i], bh[j]);
                }
        }

        scur = (scur == 2) ? 0 : scur + 1;
        sload = (sload == 2) ? 0 : sload + 1;
    }

    const int rbase = bm * 128 + wm * 64 + (lane >> 2);
    const int cbase = bn * 128 + wn * 32 + (lane & 3) * 2;
#pragma unroll
    for (int i = 0; i < 4; ++i) {
#pragma unroll
        for (int j = 0; j < 4; ++j) {
            int r = rbase + i * 16;
            int col = cbase + j * 8;
            *(float2*)&C[(size_t)r * Nc + col] =
                make_float2(acc[i][j][0], acc[i][j][1]);
            *(float2*)&C[(size_t)(r + 8) * Nc + col] =
                make_float2(acc[i][j][2], acc[i][j][3]);
        }
    }
}

// ---------------------------------------------------------------------------
// RoPE + fp16 split: fp32 qkv -> Qh/Ql (scaled), Kh, Vh in [h][s][d].
// ---------------------------------------------------------------------------
__global__ void rope_split_kernel(const float* __restrict__ qkv,
                                  const int* __restrict__ positions,
                                  __half* __restrict__ Qh, __half* __restrict__ Ql,
                                  __half* __restrict__ Kh, __half* __restrict__ Vh)
{
    int idx = blockIdx.x * blockDim.x + threadIdx.x;
    const int NHTOT = NH + 2 * NKV;  // 48
    const int TOTAL = SEQ * NHTOT * (HD / 2);
    if (idx >= TOTAL) return;

    int d = idx & 63;
    int h = (idx >> 6) % NHTOT;
    int s = idx / (NHTOT * 64);

    const float* base = qkv + (size_t)s * QKVN + h * HD;
    float x1 = base[d];
    float x2 = base[d + 64];
    float y1 = x1, y2 = x2;

    if (h < NH + NKV) {
        float pos = (float)positions[s];
        float inv = powf(10000.0f, -(2.0f * (float)d) / (float)HD);
        float ang = pos * inv;
        float c, sn;
        sincosf(ang, &sn, &c);
        y1 = x1 * c - x2 * sn;
        y2 = x2 * c + x1 * sn;
    }

    if (h < NH) {
        const float scale = 0.088388347648318447f;  // 1/sqrt(128)
        y1 *= scale; y2 *= scale;
        size_t off = ((size_t)h * SEQ + s) * HD + d;
        __half h1 = __float2half_rn(y1);
        __half h2 = __float2half_rn(y2);
        Qh[off]      = h1;
        Qh[off + 64] = h2;
        Ql[off]      = __float2half_rn(y1 - __half2float(h1));
        Ql[off + 64] = __float2half_rn(y2 - __half2float(h2));
    } else if (h < NH + NKV) {
        size_t off = ((size_t)(h - NH) * SEQ + s) * HD + d;
        Kh[off]      = __float2half_rn(y1);
        Kh[off + 64] = __float2half_rn(y2);
    } else {
        size_t off = ((size_t)(h - NH - NKV) * SEQ + s) * HD + d;
        Vh[off]      = __float2half_rn(y1);
        Vh[off + 64] = __float2half_rn(y2);
    }
}

// ---------------------------------------------------------------------------
// Tensor-core flash attention (fp16 2-term), causal, GQA. Br=Bc=64, 256 thr.
// S = Qh*Kh + Ql*Kh ; O = Ph*Vh + Pl*Vh. Double-buffered K/V.
// ---------------------------------------------------------------------------
#define APITCH 272
#define PPITCH 144
#define SSP    68
#define ATILE  (64 * APITCH)            // 17408
#define KVSTG  (2 * ATILE)              // 34816 (KH,VH)
#define O_QH   0
#define O_QL   (O_QH + ATILE)
#define O_KV0  (O_QL + ATILE)           // 34816
#define O_SS   (O_KV0 + 2 * KVSTG)      // 104448
#define O_PH   (O_SS + 64 * SSP * 4)    // 121856
#define O_PL   (O_PH + 64 * PPITCH)     // 131072
#define O_CORR (O_PL + 64 * PPITCH)     // 140288
#define O_LINV (O_CORR + 256)
#define FL_SMEM (O_LINV + 256)          // 140800

__global__ __launch_bounds__(256, 1)
void flash_mma_kernel(const __half* __restrict__ Qh, const __half* __restrict__ Ql,
                      const __half* __restrict__ Kh, const __half* __restrict__ Vh,
                      __half* __restrict__ outH, __half* __restrict__ outL)
{
    extern __shared__ char smx[];
    const uint32_t sb = s2u(smx);
    float* SsF  = (float*)(smx + O_SS);
    float* corr = (float*)(smx + O_CORR);
    float* linv = (float*)(smx + O_LINV);

    const int qb = (int)gridDim.x - 1 - (int)blockIdx.x;  // longest first
    const int h  = blockIdx.y;
    const int kvh = h / GRP;

    const int tid  = threadIdx.x;
    const int warp = tid >> 5;
    const int lane = tid & 31;
    const int wr = warp & 3;
    const int wc = warp >> 2;

    const __half* kH = Kh + (size_t)kvh * SEQ * HD;
    const __half* vH = Vh + (size_t)kvh * SEQ * HD;
    const __half* kvsrc[2] = {kH, vH};

    auto load_kv = [&](int kb, int buf) {
#pragma unroll
        for (int j = 0; j < 8; ++j) {            // 2 tiles * 1024 chunks
            int idx = tid + j * 256;
            int tsel = idx >> 10;
            int w = idx & 1023;
            int r = w >> 4, ck = w & 15;
            cpa16(sb + O_KV0 + buf * KVSTG + tsel * ATILE + r * APITCH + ck * 16,
                  kvsrc[tsel] + ((size_t)(kb * 64 + r)) * HD + ck * 8);
        }
    };

    // --- prologue: Q tiles + KV block 0 ---
    {
        const __half* qH = Qh + ((size_t)h * SEQ + qb * 64) * HD;
        const __half* qL = Ql + ((size_t)h * SEQ + qb * 64) * HD;
#pragma unroll
        for (int j = 0; j < 8; ++j) {
            int idx = tid + j * 256;
            int tsel = idx >> 10;
            int w = idx & 1023;
            int r = w >> 4, ck = w & 15;
            cpa16(sb + (tsel ? O_QL : O_QH) + r * APITCH + ck * 16,
                  (tsel ? qL : qH) + (size_t)r * HD + ck * 8);
        }
        cpa_commit();
    }
    load_kv(0, 0);
    cpa_commit();

    float m_i[8], l_i[8], oacc[8][4];
#pragma unroll
    for (int r = 0; r < 8; ++r) { m_i[r] = -1e30f; l_i[r] = 0.f; }
#pragma unroll
    for (int t = 0; t < 8; ++t)
#pragma unroll
        for (int q = 0; q < 4; ++q) oacc[t][q] = 0.f;

    for (int kb = 0; kb <= qb; ++kb) {
        const int buf = kb & 1;
        cpa_wait<0>();
        __syncthreads();

        if (kb + 1 <= qb) {
            load_kv(kb + 1, buf ^ 1);
            cpa_commit();
        }

        const uint32_t kvb = sb + O_KV0 + buf * KVSTG;

        // ---- QK: S = Qh*Kh + Ql*Kh ----
        float sf[4][4];
#pragma unroll
        for (int j = 0; j < 4; ++j)
#pragma unroll
            for (int q = 0; q < 4; ++q) sf[j][q] = 0.f;

        uint32_t aH = sb + O_QH + (wr * 16 + (lane & 15)) * APITCH + (lane >> 4) * 16;
        uint32_t aL = aH + ATILE;
        uint32_t bH = kvb + (wc * 32 + (lane & 7)) * APITCH + ((lane >> 3) & 1) * 16;
#pragma unroll
        for (int s = 0; s < 8; ++s) {
            uint32_t qh4[4], ql4[4];
            ldm_x4(qh4, aH + s * 32);
            ldm_x4(ql4, aL + s * 32);
#pragma unroll
            for (int j = 0; j < 4; ++j) {
                uint32_t kh2[2];
                ldm_x2(kh2, bH + j * 8 * APITCH + s * 32);
                mma16816(sf[j], qh4, kh2);
                mma16816(sf[j], ql4, kh2);
            }
        }

        // store S to smem with causal mask
        {
            int r0 = wr * 16 + (lane >> 2);
            int c0 = wc * 32 + (lane & 3) * 2;
            bool diag = (kb == qb);
#pragma unroll
            for (int j = 0; j < 4; ++j) {
                int c = c0 + j * 8;
                float v0 = sf[j][0], v1 = sf[j][1], v2 = sf[j][2], v3 = sf[j][3];
                if (diag) {
                    if (c > r0)         v0 = -1e30f;
                    if (c + 1 > r0)     v1 = -1e30f;
                    if (c > r0 + 8)     v2 = -1e30f;
                    if (c + 1 > r0 + 8) v3 = -1e30f;
                }
                SsF[r0 * SSP + c]           = v0;
                SsF[r0 * SSP + c + 1]       = v1;
                SsF[(r0 + 8) * SSP + c]     = v2;
                SsF[(r0 + 8) * SSP + c + 1] = v3;
            }
        }
        __syncthreads();

        // ---- softmax on owner rows ----
#pragma unroll
        for (int rr = 0; rr < 8; ++rr) {
            int r = warp * 8 + rr;
            float s0 = SsF[r * SSP + lane];
            float s1 = SsF[r * SSP + lane + 32];
            float mx = fmaxf(s0, s1);
#pragma unroll
            for (int o = 16; o > 0; o >>= 1)
                mx = fmaxf(mx, __shfl_xor_sync(0xFFFFFFFFu, mx, o));
            float m_new = fmaxf(m_i[rr], mx);
            float p0 = __expf(s0 - m_new);
            float p1 = __expf(s1 - m_new);
            SsF[r * SSP + lane]      = p0;
            SsF[r * SSP + lane + 32] = p1;
            float sum = p0 + p1;
#pragma unroll
            for (int o = 16; o > 0; o >>= 1)
                sum += __shfl_xor_sync(0xFFFFFFFFu, sum, o);
            float crr = __expf(m_i[rr] - m_new);
            l_i[rr] = l_i[rr] * crr + sum;
            m_i[rr] = m_new;
            if (lane == 0) corr[r] = crr;
        }
        __syncthreads();

        // ---- convert P -> fp16 hi/lo; scale O accumulators ----
#pragma unroll
        for (int j = 0; j < 8; ++j) {
            int i = tid + j * 256;
            int r = i >> 5;
            int c2 = (i & 31) * 2;
            float p0 = SsF[r * SSP + c2];
            float p1 = SsF[r * SSP + c2 + 1];
            __half h0 = __float2half_rn(p0);
            __half h1 = __float2half_rn(p1);
            *(__half2*)(smx + O_PH + r * PPITCH + c2 * 2) = __halves2half2(h0, h1);
            *(__half2*)(smx + O_PL + r * PPITCH + c2 * 2) =
                __halves2half2(__float2half_rn(p0 - __half2float(h0)),
                               __float2half_rn(p1 - __half2float(h1)));
        }
        {
            float cr0 = corr[wr * 16 + (lane >> 2)];
            float cr1 = corr[wr * 16 + (lane >> 2) + 8];
#pragma unroll
            for (int t = 0; t < 8; ++t) {
                oacc[t][0] *= cr0; oacc[t][1] *= cr0;
                oacc[t][2] *= cr1; oacc[t][3] *= cr1;
            }
        }
        __syncthreads();

        // ---- PV: O += Ph*Vh + Pl*Vh ----
        {
            uint32_t pH = sb + O_PH + (wr * 16 + (lane & 15)) * PPITCH + (lane >> 4) * 16;
            uint32_t pL = pH + (O_PL - O_PH);
            uint32_t vHb = kvb + ATILE + (lane & 15) * APITCH + wc * 128;
#pragma unroll
            for (int s = 0; s < 4; ++s) {
                uint32_t ph4[4], pl4[4];
                ldm_x4(ph4, pH + s * 32);
                ldm_x4(pl4, pL + s * 32);
#pragma unroll
                for (int j = 0; j < 8; ++j) {
                    uint32_t vh2[2];
                    ldm_x2t(vh2, vHb + s * 16 * APITCH + j * 16);
                    mma16816(oacc[j], ph4, vh2);
                    mma16816(oacc[j], pl4, vh2);
                }
            }
        }
    }

    // ---- epilogue ----
    __syncthreads();
    if (lane == 0) {
#pragma unroll
        for (int rr = 0; rr < 8; ++rr)
            linv[warp * 8 + rr] = 1.f / l_i[rr];
    }
    __syncthreads();

    {
        float li0 = linv[wr * 16 + (lane >> 2)];
        float li1 = linv[wr * 16 + (lane >> 2) + 8];
        int orow = qb * 64 + wr * 16 + (lane >> 2);
        int ocol = h * HD + wc * 64 + (lane & 3) * 2;
#pragma unroll
        for (int j = 0; j < 8; ++j) {
            int c = ocol + j * 8;
            float f0 = oacc[j][0] * li0, f1 = oacc[j][1] * li0;
            float f2 = oacc[j][2] * li1, f3 = oacc[j][3] * li1;
            __half h0 = __float2half_rn(f0);
            __half h1 = __float2half_rn(f1);
            __half h2 = __float2half_rn(f2);
            __half h3 = __float2half_rn(f3);
            *(__half2*)&outH[(size_t)orow * HID + c] = __halves2half2(h0, h1);
            *(__half2*)&outL[(size_t)orow * HID + c] =
                __halves2half2(__float2half_rn(f0 - __half2float(h0)),
                               __float2half_rn(f1 - __half2float(h1)));
            *(__half2*)&outH[(size_t)(orow + 8) * HID + c] = __halves2half2(h2, h3);
            *(__half2*)&outL[(size_t)(orow + 8) * HID + c] =
                __halves2half2(__float2half_rn(f2 - __half2float(h2)),
                               __float2half_rn(f3 - __half2float(h3)));
        }
    }
}

// ---------------------------------------------------------------------------
// kernel_launch
// ---------------------------------------------------------------------------
extern "C" void kernel_launch(void* const* d_in, const int* in_sizes, int n_in,
                              void* d_out, int out_size)
{
    const float* hs    = (const float*)d_in[0];
    const int*   pos   = (const int*)d_in[1];
    const float* w_qkv = (const float*)d_in[2];
    const float* w_o   = (const float*)d_in[3];
    float* out = (float*)d_out;

    float* qkv; cudaGetSymbolAddress((void**)&qkv, g_qkv);
    __half *Ah, *Al, *Bh, *Qh, *Ql, *Kh, *Vh;
    cudaGetSymbolAddress((void**)&Ah, g_Ah);
    cudaGetSymbolAddress((void**)&Al, g_Al);
    cudaGetSymbolAddress((void**)&Bh, g_Bh);
    cudaGetSymbolAddress((void**)&Qh, g_Qh);
    cudaGetSymbolAddress((void**)&Ql, g_Ql);
    cudaGetSymbolAddress((void**)&Kh, g_Kh);
    cudaGetSymbolAddress((void**)&Vh, g_Vh);

    cudaFuncSetAttribute(gemm_mma_kernel,
                         cudaFuncAttributeMaxDynamicSharedMemorySize, GEMM_SMEM);
    cudaFuncSetAttribute(flash_mma_kernel,
                         cudaFuncAttributeMaxDynamicSharedMemorySize, FL_SMEM);

    // 1) split hs ; transpose w_qkv (fp16 hi only)
    split_kernel<<<(SEQ * HID / 4 + 255) / 256, 256>>>(hs, Ah, Al, SEQ * HID / 4);
    transT_kernel<<<dim3(QKVN / 32, HID / 32), dim3(32, 8)>>>(w_qkv, Bh, HID, QKVN);

    // 2) QKV projection (tensor cores, fp16 2-term)
    gemm_mma_kernel<<<dim3(QKVN / 128, SEQ / 128), 256, GEMM_SMEM>>>(
        Ah, Al, Bh, qkv, HID, QKVN);

    // 3) RoPE + split into fp16 Q(hi/lo)/K/V [h][s][d]
    {
        int total = SEQ * (NH + 2 * NKV) * (HD / 2);
        rope_split_kernel<<<(total + 255) / 256, 256>>>(qkv, pos, Qh, Ql, Kh, Vh);
    }

    // 4) Tensor-core flash attention -> fp16 hi/lo directly into Ah/Al
    flash_mma_kernel<<<dim3(SEQ / 64, NH), 256, FL_SMEM>>>(
        Qh, Ql, Kh, Vh, Ah, Al);

    // 5) transpose w_o (fp16 hi only)
    transT_kernel<<<dim3(HID / 32, HID / 32), dim3(32, 8)>>>(w_o, Bh, HID, HID);

    // 6) Output projection (tensor cores, fp16 2-term)
    gemm_mma_kernel<<<dim3(HID / 128, SEQ / 128), 256, GEMM_SMEM>>>(
        Ah, Al, Bh, out, HID, HID);
}